// round 13
// baseline (speedup 1.0000x reference)
#include <cuda_runtime.h>
#include <cuda_bf16.h>
#include <cstdint>

#define NTOT 61440
#define NODES 30
#define BATCH 2048
#define INCH 12
#define EDGES 491520
#define C0 128
#define C1 512
#define C2 128
#define FCIN (C2*NODES)
#define FCOUT 72
#define NB_LIN 240
#define NB_DEG 1920

typedef unsigned long long ull;
typedef unsigned short u16;
typedef uint32_t u32;

__device__ float g_h[NTOT*INCH];
__device__ float g_deg[NTOT];
__device__ float g_dinv[NTOT];
__device__ float g_A0[NTOT*INCH];
__device__ float g_X1[(size_t)C0*NODES*BATCH];    // [c][t][b] f32 (scalar consumers)
__device__ float g_X2[(size_t)C1*NODES*BATCH];
__device__ float g_X3[(size_t)C2*NODES*BATCH];
__device__ ull g_X1s3[(size_t)NODES*BATCH*(3*C0/4)];   // [t][b] rows of 3*C0 u16 slots
__device__ ull g_X2s3[(size_t)NODES*BATCH*(3*C1/4)];
__device__ ull g_W1s[(size_t)C1*4*(3*C0/4)];           // [oc][g] rows of 3*IN u16 slots
__device__ ull g_W2s[(size_t)C2*4*(3*C1/4)];

// ---------- helpers ----------
__device__ __forceinline__ ull dup2(float v){ ull r; asm("mov.b64 %0,{%1,%1};":"=l"(r):"f"(v)); return r; }
__device__ __forceinline__ void unpack2(ull v,float&lo,float&hi){ asm("mov.b64 {%0,%1},%2;":"=f"(lo),"=f"(hi):"l"(v)); }
__device__ __forceinline__ void fma2(ull&d,ull a,ull b){ asm("fma.rn.f32x2 %0,%1,%2,%0;":"+l"(d):"l"(a),"l"(b)); }
__device__ __forceinline__ void bsplit(float v,u16&h,u16&l){
    __nv_bfloat16 bh=__float2bfloat16(v); float fh=__bfloat162float(bh);
    __nv_bfloat16 bl=__float2bfloat16(v-fh);
    h=*(u16*)&bh; l=*(u16*)&bl;
}
__device__ __forceinline__ void ldmx4(u32* r, u32 addr){
    asm volatile("ldmatrix.sync.aligned.m8n8.x4.shared.b16 {%0,%1,%2,%3}, [%4];"
        :"=r"(r[0]),"=r"(r[1]),"=r"(r[2]),"=r"(r[3]):"r"(addr));
}
__device__ __forceinline__ void mma16816(float* d, const u32* a, const u32* b){
    asm volatile("mma.sync.aligned.m16n8k16.row.col.f32.bf16.bf16.f32 "
        "{%0,%1,%2,%3},{%4,%5,%6,%7},{%8,%9},{%0,%1,%2,%3};"
        :"+f"(d[0]),"+f"(d[1]),"+f"(d[2]),"+f"(d[3])
        :"r"(a[0]),"r"(a[1]),"r"(a[2]),"r"(a[3]),"r"(b[0]),"r"(b[1]));
}
#define SW(q,r) ((((( (q)>>1)^((r)&7))<<1))|((q)&1))

// ---------- GCN front ----------
__global__ void k_pre(const float* __restrict__ x, const float* __restrict__ w,
                      const int* __restrict__ dst){
    int bid=blockIdx.x;
    if(bid<NB_LIN){
        __shared__ float sw[INCH*INCH];
        if(threadIdx.x<INCH*INCH) sw[threadIdx.x]=w[threadIdx.x];
        __syncthreads();
        int n=bid*blockDim.x+threadIdx.x; if(n>=NTOT) return;
        float xr[INCH];
#pragma unroll
        for(int i=0;i<INCH;i++) xr[i]=x[n*INCH+i];
#pragma unroll
        for(int c=0;c<INCH;c++){
            float s=0.f;
#pragma unroll
            for(int i=0;i<INCH;i++) s=fmaf(sw[c*INCH+i],xr[i],s);
            g_h[n*INCH+c]=s;
        }
    } else {
        int e=(bid-NB_LIN)*blockDim.x+threadIdx.x;
        if(e<EDGES) atomicAdd(&g_deg[dst[e]],1.0f);
    }
}
__global__ void k_dinv_init(const float* __restrict__ gcn_b){
    int n=blockIdx.x*blockDim.x+threadIdx.x; if(n>=NTOT) return;
    float di=rsqrtf(g_deg[n]+1.0f);
    g_dinv[n]=di; float s=di*di;
#pragma unroll
    for(int c=0;c<INCH;c++) g_A0[n*INCH+c]=fmaf(s,g_h[n*INCH+c],gcn_b[c]);
}
__global__ void k_scatter(const int* __restrict__ src, const int* __restrict__ dst){
    int id=blockIdx.x*blockDim.x+threadIdx.x; if(id>=EDGES*INCH) return;
    int e=id/INCH, c=id%INCH;
    int s=src[e], d=dst[e];
    atomicAdd(&g_A0[d*INCH+c], g_dinv[s]*g_dinv[d]*g_h[s*INCH+c]);
}

// ---------- weight split: 3-slot streams (wh,wh,wl) ----------
__global__ void k_wsplit(const float* __restrict__ cw1, const float* __restrict__ dw1,
                         const float* __restrict__ cw2, const float* __restrict__ dw2){
    int i=blockIdx.x*256+threadIdx.x;
    if(i<C1*4*C0){
        int oc=i/(4*C0), g=(i/C0)%4, ic=i%C0;
        float w = g<3 ? cw1[(oc*C0+ic)*3+g] : dw1[oc*C0+ic];
        u16 h,l; bsplit(w,h,l);
        u16* W=(u16*)g_W1s; size_t b=((size_t)oc*4+g)*(3*C0)+3*ic;
        W[b]=h; W[b+1]=h; W[b+2]=l;
    } else {
        i-=C1*4*C0;
        if(i<C2*4*C1){
            int oc=i/(4*C1), g=(i/C1)%4, ic=i%C1;
            float w = g<3 ? cw2[(oc*C1+ic)*3+g] : dw2[oc*C1+ic];
            u16 h,l; bsplit(w,h,l);
            u16* W=(u16*)g_W2s; size_t b=((size_t)oc*4+g)*(3*C1)+3*ic;
            W[b]=h; W[b+1]=h; W[b+2]=l;
        }
    }
}

// ---------- scalar FFMA body ----------
template<int IN,int DIL,bool A0MODE>
__device__ __forceinline__ void tcnS(const float* __restrict__ Xin, float* __restrict__ Xout,
      const float* __restrict__ cw, const float* __restrict__ cb,
      const float* __restrict__ dw, const float* __restrict__ db, char* smem){
    constexpr int BN=128, BM=64, NT=256, BK=(IN<16)?IN:8;
    float* A_s=(float*)smem;                                   // BK*3*BN floats
    float* B_s=(float*)(smem + (size_t)BK*3*BN*sizeof(float)); // BM*BK*8 floats
    const int t=blockIdx.x, b0=blockIdx.y*BN, oc0=blockIdx.z*BM;
    const int tid=threadIdx.x, tx=tid&31, ty=tid>>5;
    const int bb=tx*4, oct=ty*8;
    ull acc1[8][2], acc2[8][2];
#pragma unroll
    for(int j=0;j<8;j++){acc1[j][0]=acc1[j][1]=acc2[j][0]=acc2[j][1]=0ULL;}
    for(int ic0=0;ic0<IN;ic0+=BK){
        for(int i=tid;i<BK*3*BN;i+=NT){
            int ic=i/(3*BN), r=i%(3*BN), kk=r/BN, b=r%BN;
            int tk=t+(kk-2)*DIL;
            float v=0.f;
            if(tk>=0){
                if(A0MODE) v=g_A0[((size_t)(b0+b)*NODES+tk)*INCH+ic0+ic];
                else       v=Xin[((size_t)(ic0+ic)*NODES+tk)*BATCH+b0+b];
            }
            A_s[i]=v;
        }
        for(int i=tid;i<BM*BK*4;i+=NT){
            int oc=i/(BK*4), r=i%(BK*4), ic=r/4, w=r&3;
            float v=(w<3)?cw[((size_t)(oc0+oc)*IN+ic0+ic)*3+w]:dw[(size_t)(oc0+oc)*IN+ic0+ic];
            *reinterpret_cast<ull*>(&B_s[i*2])=dup2(v);
        }
        __syncthreads();
#pragma unroll
        for(int ic=0;ic<BK;ic++){
            ulonglong2 a0=*reinterpret_cast<const ulonglong2*>(&A_s[(ic*3+0)*BN+bb]);
            ulonglong2 a1=*reinterpret_cast<const ulonglong2*>(&A_s[(ic*3+1)*BN+bb]);
            ulonglong2 a2=*reinterpret_cast<const ulonglong2*>(&A_s[(ic*3+2)*BN+bb]);
#pragma unroll
            for(int j=0;j<8;j++){
                const float* wb=&B_s[((oct+j)*BK+ic)*8];
                ulonglong2 wA=*reinterpret_cast<const ulonglong2*>(wb);
                ulonglong2 wB=*reinterpret_cast<const ulonglong2*>(wb+4);
                fma2(acc1[j][0],wA.x,a0.x); fma2(acc1[j][1],wA.x,a0.y);
                fma2(acc1[j][0],wA.y,a1.x); fma2(acc1[j][1],wA.y,a1.y);
                fma2(acc1[j][0],wB.x,a2.x); fma2(acc1[j][1],wB.x,a2.y);
                fma2(acc2[j][0],wB.y,a2.x); fma2(acc2[j][1],wB.y,a2.y);
            }
        }
        __syncthreads();
    }
#pragma unroll
    for(int j=0;j<8;j++){
        int oc=oc0+oct+j;
        float cbv=cb[oc], dbv=db[oc];
        float c0,c1,c2,c3,d0,d1,d2,d3;
        unpack2(acc1[j][0],c0,c1); unpack2(acc1[j][1],c2,c3);
        unpack2(acc2[j][0],d0,d1); unpack2(acc2[j][1],d2,d3);
        float4 o;
        o.x=fmaxf(fmaxf(c0+cbv,0.f)+d0+dbv,0.f);
        o.y=fmaxf(fmaxf(c1+cbv,0.f)+d1+dbv,0.f);
        o.z=fmaxf(fmaxf(c2+cbv,0.f)+d2+dbv,0.f);
        o.w=fmaxf(fmaxf(c3+cbv,0.f)+d3+dbv,0.f);
        *reinterpret_cast<float4*>(&Xout[((size_t)oc*NODES+t)*BATCH+b0+bb])=o;
        if(A0MODE){   // tcn0: also emit 3-slot stream for tensor-path tcn1
            u16* P=(u16*)g_X1s3;
#pragma unroll
            for(int i=0;i<4;i++){
                u16 h,l; bsplit((&o.x)[i],h,l);
                size_t p=((size_t)t*BATCH+b0+bb+i)*(3*C0)+3*oc;
                P[p]=h; P[p+1]=l; P[p+2]=h;
            }
        }
    }
}

// ---------- tensor body: 3-slot K, merged tap2+down ----------
template<int IN,int DIL,int OUTM>
__device__ __forceinline__ void tcnT(const ull* __restrict__ Xs, const ull* __restrict__ Ws,
      const float* __restrict__ cb, const float* __restrict__ db, char* smem){
    constexpr int RW=3*IN/4, CH=RW/16;       // u64s per row, 64-slot chunks per row
    ull* A_s=(ull*)smem;                     // 2048 ull = 16KB
    ull* B_s=(ull*)(smem+16384);             // 1024 ull = 8KB
    ull* B2_s=(ull*)(smem+24576);            // 8KB
    const int t=blockIdx.x, b0=blockIdx.y*128, oc0=blockIdx.z*64;
    const int tid=threadIdx.x, lane=tid&31, w=tid>>5;
    const int mw=w&3, nw=w>>2;
    const u32 Ab=(u32)__cvta_generic_to_shared(A_s);
    const u32 Bb=(u32)__cvta_generic_to_shared(B_s);
    const u32 B2b=(u32)__cvta_generic_to_shared(B2_s);
    const int sub=lane>>3, l7=lane&7;
    const int rA0=mw*32+l7+((sub&1)<<3);
    const int rB0=nw*32+l7+((sub>>1)<<3);
    const int uA=sub>>1, uB=sub&1;
    float accD[2][4][4]={}, accE[2][4][4]={};
#pragma unroll 1
    for(int g=0;g<3;g++){
        const int tk=t-(2-g)*DIL;
#pragma unroll 1
        for(int kc=0;kc<CH;kc++){
            __syncthreads();
            for(int i=tid;i<2048;i+=256){
                int b=i>>4, q=i&15;
                ull v=0ULL;
                if(tk>=0) v=Xs[((size_t)tk*BATCH+b0+b)*RW+kc*16+q];
                A_s[(b<<4)+SW(q,b)]=v;
            }
            for(int i=tid;i<1024;i+=256){
                int n=i>>4, q=i&15;
                B_s[(n<<4)+SW(q,n)]=Ws[((size_t)(oc0+n)*4+g)*RW+kc*16+q];
            }
            if(g==2) for(int i=tid;i<1024;i+=256){
                int n=i>>4, q=i&15;
                B2_s[(n<<4)+SW(q,n)]=Ws[((size_t)(oc0+n)*4+3)*RW+kc*16+q];
            }
            __syncthreads();
#pragma unroll
            for(int s=0;s<4;s++){
                u32 Af[2][4], Bf[2][4];
#pragma unroll
                for(int mi=0;mi<2;mi++){
                    int r=rA0+mi*16, u=2*s+uA;
                    ldmx4(Af[mi], Ab+(u32)(r*128+((u^(r&7))<<4)));
                }
#pragma unroll
                for(int p=0;p<2;p++){
                    int r=rB0+p*16, u=2*s+uB;
                    ldmx4(Bf[p], Bb+(u32)(r*128+((u^(r&7))<<4)));
                }
#pragma unroll
                for(int mi=0;mi<2;mi++)
#pragma unroll
                for(int ni=0;ni<4;ni++)
                    mma16816(accD[mi][ni], Af[mi], &Bf[ni>>1][(ni&1)*2]);
                if(g==2){
                    u32 Cf[2][4];
#pragma unroll
                    for(int p=0;p<2;p++){
                        int r=rB0+p*16, u=2*s+uB;
                        ldmx4(Cf[p], B2b+(u32)(r*128+((u^(r&7))<<4)));
                    }
#pragma unroll
                    for(int mi=0;mi<2;mi++)
#pragma unroll
                    for(int ni=0;ni<4;ni++)
                        mma16816(accE[mi][ni], Af[mi], &Cf[ni>>1][(ni&1)*2]);
                }
            }
        }
    }
    const int qr=lane>>2, qc=(lane&3)*2;
#pragma unroll
    for(int mi=0;mi<2;mi++)
#pragma unroll
    for(int ni=0;ni<4;ni++){
        int oc=oc0+nw*32+ni*8+qc;
        int b =b0+mw*32+mi*16+qr;
        float cb0=cb[oc], cb1=cb[oc+1], db0=db[oc], db1=db[oc+1];
        const float* D=accD[mi][ni]; const float* E=accE[mi][ni];
        float v00=fmaxf(fmaxf(D[0]+cb0,0.f)+E[0]+db0,0.f);
        float v01=fmaxf(fmaxf(D[1]+cb1,0.f)+E[1]+db1,0.f);
        float v10=fmaxf(fmaxf(D[2]+cb0,0.f)+E[2]+db0,0.f);
        float v11=fmaxf(fmaxf(D[3]+cb1,0.f)+E[3]+db1,0.f);
        if(OUTM==0){
            u16 h0,l0,h1,l1;
            u32* P0=(u32*)((u16*)g_X2s3+((size_t)t*BATCH+b)*(3*C1)+3*oc);
            bsplit(v00,h0,l0); bsplit(v01,h1,l1);
            P0[0]=(u32)h0|((u32)l0<<16); P0[1]=(u32)h0|((u32)h1<<16); P0[2]=(u32)l1|((u32)h1<<16);
            u32* P1=(u32*)((u16*)g_X2s3+((size_t)t*BATCH+b+8)*(3*C1)+3*oc);
            bsplit(v10,h0,l0); bsplit(v11,h1,l1);
            P1[0]=(u32)h0|((u32)l0<<16); P1[1]=(u32)h0|((u32)h1<<16); P1[2]=(u32)l1|((u32)h1<<16);
        } else {
            g_X3[((size_t)oc*NODES+t)*BATCH+b]=v00;
            g_X3[((size_t)(oc+1)*NODES+t)*BATCH+b]=v01;
            g_X3[((size_t)oc*NODES+t)*BATCH+b+8]=v10;
            g_X3[((size_t)(oc+1)*NODES+t)*BATCH+b+8]=v11;
        }
    }
}

// ---------- kernels: species by y PARITY (interleaved across waves) ----------
__global__ void __launch_bounds__(256,2)
k_tcn0(const float* __restrict__ cw, const float* __restrict__ cb,
       const float* __restrict__ dw, const float* __restrict__ db){
    __shared__ __align__(16) char smem[43008];   // A 18432 + B 24576 (BK=12)
    tcnS<INCH,1,true>(nullptr, g_X1, cw, cb, dw, db, smem);
}
__global__ void __launch_bounds__(256,2)
k_tcn1(const float* __restrict__ cw, const float* __restrict__ cb,
       const float* __restrict__ dw, const float* __restrict__ db){
    __shared__ __align__(16) char smem[32768];
    if((blockIdx.y&1)==0) tcnT<C0,3,0>(g_X1s3, g_W1s, cb, db, smem);
    else                  tcnS<C0,3,false>(g_X1, g_X2, cw, cb, dw, db, smem);
}
__global__ void __launch_bounds__(256,2)
k_tcn2(const float* __restrict__ cw, const float* __restrict__ cb,
       const float* __restrict__ dw, const float* __restrict__ db){
    __shared__ __align__(16) char smem[32768];
    if((blockIdx.y&1)==0) tcnT<C1,9,1>(g_X2s3, g_W2s, cb, db, smem);
    else                  tcnS<C1,9,false>(g_X2, g_X3, cw, cb, dw, db, smem);
}

// ---------- FC ----------
#define FC_BM 32
#define FC_BK 32
__global__ void __launch_bounds__(256)
k_fc(const float* __restrict__ W, const float* __restrict__ bias, float* __restrict__ out){
    const float* T=g_X3;
    __shared__ float Ts[FC_BK][FC_BM+1];
    __shared__ float Ws2[80][FC_BK+1];
    int b0=blockIdx.x*FC_BM, tid=threadIdx.x, tr=tid/16, tc=tid%16;
    float acc[2][5]={};
    for(int k0=0;k0<FCIN;k0+=FC_BK){
        for(int i=tid;i<FC_BK*FC_BM;i+=256){
            int k=i/FC_BM, m=i%FC_BM;
            Ts[k][m]=T[(size_t)(k0+k)*BATCH+b0+m];
        }
        for(int i=tid;i<80*FC_BK;i+=256){
            int n=i/FC_BK, k=i%FC_BK;
            Ws2[n][k]=(n<FCOUT)?W[(size_t)n*FCIN+k0+k]:0.f;
        }
        __syncthreads();
#pragma unroll
        for(int kk=0;kk<FC_BK;kk++){
            float a0=Ts[kk][tr*2+0], a1=Ts[kk][tr*2+1];
#pragma unroll
            for(int j=0;j<5;j++){
                float bv=Ws2[tc*5+j][kk];
                acc[0][j]=fmaf(a0,bv,acc[0][j]);
                acc[1][j]=fmaf(a1,bv,acc[1][j]);
            }
        }
        __syncthreads();
    }
#pragma unroll
    for(int i=0;i<2;i++){
        int b=b0+tr*2+i;
#pragma unroll
        for(int j=0;j<5;j++){
            int o=tc*5+j;
            if(o<FCOUT) out[(size_t)b*FCOUT+o]=acc[i][j]+bias[o];
        }
    }
    for(int i=blockIdx.x*256+tid;i<NTOT;i+=gridDim.x*256) g_deg[i]=0.f;
}

// ---------- launch ----------
extern "C" void kernel_launch(void* const* d_in, const int* in_sizes, int n_in,
                              void* d_out, int out_size){
    const float* x=(const float*)d_in[0];
    const int* ei=(const int*)d_in[1];
    const float* gcn_w=(const float*)d_in[2];
    const float* gcn_b=(const float*)d_in[3];
    const float* cw0=(const float*)d_in[4];
    const float* cb0=(const float*)d_in[5];
    const float* dw0=(const float*)d_in[6];
    const float* db0=(const float*)d_in[7];
    const float* cw1=(const float*)d_in[8];
    const float* cb1=(const float*)d_in[9];
    const float* dw1=(const float*)d_in[10];
    const float* db1=(const float*)d_in[11];
    const float* cw2=(const float*)d_in[12];
    const float* cb2=(const float*)d_in[13];
    const float* dw2=(const float*)d_in[14];
    const float* db2=(const float*)d_in[15];
    const float* fc_w=(const float*)d_in[16];
    const float* fc_b=(const float*)d_in[17];
    float* out=(float*)d_out;
    const int* src=ei;
    const int* dst=ei+EDGES;

    k_pre<<<NB_LIN+NB_DEG,256>>>(x,gcn_w,dst);
    k_dinv_init<<<(NTOT+255)/256,256>>>(gcn_b);
    k_scatter<<<(EDGES*INCH+255)/256,256>>>(src,dst);
    k_wsplit<<<(C1*4*C0+C2*4*C1+255)/256,256>>>(cw1,dw1,cw2,dw2);
    k_tcn0<<<dim3(NODES,BATCH/128,C0/64),256>>>(cw0,cb0,dw0,db0);
    k_tcn1<<<dim3(NODES,BATCH/128,C1/64),256>>>(cw1,cb1,dw1,db1);
    k_tcn2<<<dim3(NODES,BATCH/128,C2/64),256>>>(cw2,cb2,dw2,db2);
    k_fc<<<BATCH/FC_BM,256>>>(fc_w,fc_b,out);
}

// round 14
// speedup vs baseline: 1.5221x; 1.5221x over previous
#include <cuda_runtime.h>
#include <cuda_fp16.h>
#include <cstdint>

#define NTOT 61440
#define NODES 30
#define BATCH 2048
#define INCH 12
#define EDGES 491520
#define C0 128
#define C1 512
#define C2 128
#define FCIN (C2*NODES)
#define FCOUT 72
#define NB_LIN 240
#define NB_DEG 1920
#define NB_WS 2048

typedef unsigned long long ull;
typedef unsigned short u16;
typedef uint32_t u32;

__device__ float g_h[NTOT*INCH];
__device__ float g_deg[NTOT];               // zeroed by k_fc tail
__device__ float g_A0[NTOT*INCH];           // zeroed by k_fc tail
__device__ float g_X3[(size_t)C2*NODES*BATCH];          // [c][t][b]
__device__ ull g_X1s[(size_t)NODES*BATCH*(C0/2)];       // [t][b][ic] (xh,xl) f16 pairs
__device__ ull g_X2s[(size_t)NODES*BATCH*(C1/2)];
__device__ ull g_W1s[(size_t)C1*4*(C0/2)];              // [oc][g][ic] (wh,wh)
__device__ ull g_W2s[(size_t)C2*4*(C1/2)];

// ---------- helpers ----------
__device__ __forceinline__ ull dup2(float v){ ull r; asm("mov.b64 %0,{%1,%1};":"=l"(r):"f"(v)); return r; }
__device__ __forceinline__ void unpack2(ull v,float&lo,float&hi){ asm("mov.b64 {%0,%1},%2;":"=f"(lo),"=f"(hi):"l"(v)); }
__device__ __forceinline__ void fma2(ull&d,ull a,ull b){ asm("fma.rn.f32x2 %0,%1,%2,%0;":"+l"(d):"l"(a),"l"(b)); }
__device__ __forceinline__ u32 packA2(float v){       // (xh, xl) f16 pair
    __half h=__float2half_rn(v);
    __half l=__float2half_rn(v-__half2float(h));
    return (u32)__half_as_ushort(h) | ((u32)__half_as_ushort(l)<<16);
}
__device__ __forceinline__ u32 packW2(float v){       // (wh, wh)
    __half h=__float2half_rn(v);
    u32 s=__half_as_ushort(h);
    return s|(s<<16);
}
__device__ __forceinline__ void ldmx4(u32* r, u32 addr){
    asm volatile("ldmatrix.sync.aligned.m8n8.x4.shared.b16 {%0,%1,%2,%3}, [%4];"
        :"=r"(r[0]),"=r"(r[1]),"=r"(r[2]),"=r"(r[3]):"r"(addr));
}
__device__ __forceinline__ void mma16816(float* d, const u32* a, const u32* b){
    asm volatile("mma.sync.aligned.m16n8k16.row.col.f32.f16.f16.f32 "
        "{%0,%1,%2,%3},{%4,%5,%6,%7},{%8,%9},{%0,%1,%2,%3};"
        :"+f"(d[0]),"+f"(d[1]),"+f"(d[2]),"+f"(d[3])
        :"r"(a[0]),"r"(a[1]),"r"(a[2]),"r"(a[3]),"r"(b[0]),"r"(b[1]));
}
#define SW(q,r) ((((( (q)>>1)^((r)&7))<<1))|((q)&1))

// ---------- launch 1: GCN linear | degree count | weight split ----------
__global__ void k_pre(const float* __restrict__ x, const float* __restrict__ w,
                      const int* __restrict__ dst,
                      const float* __restrict__ cw1, const float* __restrict__ dw1,
                      const float* __restrict__ cw2, const float* __restrict__ dw2){
    int bid=blockIdx.x;
    if(bid<NB_LIN){
        __shared__ float sw[INCH*INCH];
        if(threadIdx.x<INCH*INCH) sw[threadIdx.x]=w[threadIdx.x];
        __syncthreads();
        int n=bid*blockDim.x+threadIdx.x; if(n>=NTOT) return;
        float xr[INCH];
#pragma unroll
        for(int i=0;i<INCH;i++) xr[i]=x[n*INCH+i];
#pragma unroll
        for(int c=0;c<INCH;c++){
            float s=0.f;
#pragma unroll
            for(int i=0;i<INCH;i++) s=fmaf(sw[c*INCH+i],xr[i],s);
            g_h[n*INCH+c]=s;
        }
    } else if(bid<NB_LIN+NB_DEG){
        int e=(bid-NB_LIN)*blockDim.x+threadIdx.x;
        if(e<EDGES) atomicAdd(&g_deg[dst[e]],1.0f);
    } else {
        int i=(bid-NB_LIN-NB_DEG)*256+threadIdx.x;
        if(i<C1*4*C0){
            int oc=i/(4*C0), g=(i/C0)%4, ic=i%C0;
            float v = g<3 ? cw1[(oc*C0+ic)*3+g] : dw1[oc*C0+ic];
            ((u32*)g_W1s)[((size_t)oc*4+g)*C0+ic]=packW2(v);
        } else {
            i-=C1*4*C0;
            if(i<C2*4*C1){
                int oc=i/(4*C1), g=(i/C1)%4, ic=i%C1;
                float v = g<3 ? cw2[(oc*C1+ic)*3+g] : dw2[oc*C1+ic];
                ((u32*)g_W2s)[((size_t)oc*4+g)*C1+ic]=packW2(v);
            }
        }
    }
}

// ---------- launch 2: node init + edge scatter (pure atomics; g_A0 pre-zeroed) ----------
__global__ void k_scatter(const int* __restrict__ src, const int* __restrict__ dst,
                          const float* __restrict__ gcn_b){
    int bid=blockIdx.x;
    if(bid<NB_LIN){
        int n=bid*256+threadIdx.x; if(n>=NTOT) return;
        float di2=__frcp_rn(g_deg[n]+1.0f);   // self-loop term 1/(deg+1)
#pragma unroll
        for(int c=0;c<INCH;c++)
            atomicAdd(&g_A0[n*INCH+c], fmaf(di2,g_h[n*INCH+c],gcn_b[c]));
    } else {
        int e=(bid-NB_LIN)*256+threadIdx.x; if(e>=EDGES) return;
        int s=src[e], d=dst[e];
        float sc=rsqrtf(g_deg[s]+1.0f)*rsqrtf(g_deg[d]+1.0f);
#pragma unroll
        for(int c=0;c<INCH;c++)
            atomicAdd(&g_A0[d*INCH+c], sc*g_h[s*INCH+c]);
    }
}

// ---------- launch 3: tcn0 scalar (12->128), emits f16-pair stream ----------
__global__ void __launch_bounds__(256,2)
k_tcn0(const float* __restrict__ cw, const float* __restrict__ cb,
       const float* __restrict__ dw, const float* __restrict__ db){
    constexpr int IN=INCH, BN=128, BM=64, NT=256, BK=12;
    __shared__ __align__(16) char smem[43008];
    float* A_s=(float*)smem;                 // 18432
    float* B_s=(float*)(smem+18432);         // 24576
    const int t=blockIdx.x, b0=blockIdx.y*BN, oc0=blockIdx.z*BM;
    const int tid=threadIdx.x, tx=tid&31, ty=tid>>5;
    const int bb=tx*4, oct=ty*8;
    ull acc1[8][2], acc2[8][2];
#pragma unroll
    for(int j=0;j<8;j++){acc1[j][0]=acc1[j][1]=acc2[j][0]=acc2[j][1]=0ULL;}
    for(int i=tid;i<BK*3*BN;i+=NT){
        int ic=i/(3*BN), r=i%(3*BN), kk=r/BN, b=r%BN;
        int tk=t+(kk-2);
        A_s[i]=(tk>=0)?g_A0[((size_t)(b0+b)*NODES+tk)*IN+ic]:0.f;
    }
    for(int i=tid;i<BM*BK*4;i+=NT){
        int oc=i/(BK*4), r=i%(BK*4), ic=r/4, w=r&3;
        float v=(w<3)?cw[((size_t)(oc0+oc)*IN+ic)*3+w]:dw[(size_t)(oc0+oc)*IN+ic];
        *reinterpret_cast<ull*>(&B_s[i*2])=dup2(v);
    }
    __syncthreads();
#pragma unroll
    for(int ic=0;ic<BK;ic++){
        ulonglong2 a0=*reinterpret_cast<const ulonglong2*>(&A_s[(ic*3+0)*BN+bb]);
        ulonglong2 a1=*reinterpret_cast<const ulonglong2*>(&A_s[(ic*3+1)*BN+bb]);
        ulonglong2 a2=*reinterpret_cast<const ulonglong2*>(&A_s[(ic*3+2)*BN+bb]);
#pragma unroll
        for(int j=0;j<8;j++){
            const float* wb=&B_s[((oct+j)*BK+ic)*8];
            ulonglong2 wA=*reinterpret_cast<const ulonglong2*>(wb);
            ulonglong2 wB=*reinterpret_cast<const ulonglong2*>(wb+4);
            fma2(acc1[j][0],wA.x,a0.x); fma2(acc1[j][1],wA.x,a0.y);
            fma2(acc1[j][0],wA.y,a1.x); fma2(acc1[j][1],wA.y,a1.y);
            fma2(acc1[j][0],wB.x,a2.x); fma2(acc1[j][1],wB.x,a2.y);
            fma2(acc2[j][0],wB.y,a2.x); fma2(acc2[j][1],wB.y,a2.y);
        }
    }
    u32* P=(u32*)g_X1s;
#pragma unroll
    for(int j=0;j<8;j++){
        int oc=oc0+oct+j;
        float cbv=cb[oc], dbv=db[oc];
        float c0,c1,c2,c3,d0,d1,d2,d3;
        unpack2(acc1[j][0],c0,c1); unpack2(acc1[j][1],c2,c3);
        unpack2(acc2[j][0],d0,d1); unpack2(acc2[j][1],d2,d3);
        float o[4]={fmaxf(fmaxf(c0+cbv,0.f)+d0+dbv,0.f), fmaxf(fmaxf(c1+cbv,0.f)+d1+dbv,0.f),
                    fmaxf(fmaxf(c2+cbv,0.f)+d2+dbv,0.f), fmaxf(fmaxf(c3+cbv,0.f)+d3+dbv,0.f)};
#pragma unroll
        for(int i=0;i<4;i++)
            P[((size_t)t*BATCH+b0+bb+i)*C0+oc]=packA2(o[i]);
    }
}

// ---------- tensor TCN: f16 2-slot, merged tap2+down ----------
template<int IN,int DIL,int OUTM>
__device__ __forceinline__ void tcnT(const ull* __restrict__ Xs, const ull* __restrict__ Ws,
      const float* __restrict__ cb, const float* __restrict__ db, char* smem){
    constexpr int RW=IN/2, CH=RW/16;         // u64s per row, 16-u64 chunks
    ull* A_s=(ull*)smem;                     // 16KB
    ull* B_s=(ull*)(smem+16384);             // 8KB
    ull* B2_s=(ull*)(smem+24576);            // 8KB
    const int t=blockIdx.x, b0=blockIdx.y*128, oc0=blockIdx.z*64;
    const int tid=threadIdx.x, lane=tid&31, w=tid>>5;
    const int mw=w&3, nw=w>>2;
    const u32 Ab=(u32)__cvta_generic_to_shared(A_s);
    const u32 Bb=(u32)__cvta_generic_to_shared(B_s);
    const u32 B2b=(u32)__cvta_generic_to_shared(B2_s);
    const int sub=lane>>3, l7=lane&7;
    const int rA0=mw*32+l7+((sub&1)<<3);
    const int rB0=nw*32+l7+((sub>>1)<<3);
    const int uA=sub>>1, uB=sub&1;
    float accD[2][4][4]={}, accE[2][4][4]={};
#pragma unroll 1
    for(int g=0;g<3;g++){
        const int tk=t-(2-g)*DIL;
#pragma unroll 1
        for(int kc=0;kc<CH;kc++){
            __syncthreads();
            for(int i=tid;i<2048;i+=256){
                int b=i>>4, q=i&15;
                ull v=0ULL;
                if(tk>=0) v=Xs[((size_t)tk*BATCH+b0+b)*RW+kc*16+q];
                A_s[(b<<4)+SW(q,b)]=v;
            }
            for(int i=tid;i<1024;i+=256){
                int n=i>>4, q=i&15;
                B_s[(n<<4)+SW(q,n)]=Ws[((size_t)(oc0+n)*4+g)*RW+kc*16+q];
            }
            if(g==2) for(int i=tid;i<1024;i+=256){
                int n=i>>4, q=i&15;
                B2_s[(n<<4)+SW(q,n)]=Ws[((size_t)(oc0+n)*4+3)*RW+kc*16+q];
            }
            __syncthreads();
#pragma unroll
            for(int s=0;s<4;s++){
                u32 Af[2][4], Bf[2][4];
#pragma unroll
                for(int mi=0;mi<2;mi++){
                    int r=rA0+mi*16, u=2*s+uA;
                    ldmx4(Af[mi], Ab+(u32)(r*128+((u^(r&7))<<4)));
                }
#pragma unroll
                for(int p=0;p<2;p++){
                    int r=rB0+p*16, u=2*s+uB;
                    ldmx4(Bf[p], Bb+(u32)(r*128+((u^(r&7))<<4)));
                }
#pragma unroll
                for(int mi=0;mi<2;mi++)
#pragma unroll
                for(int ni=0;ni<4;ni++)
                    mma16816(accD[mi][ni], Af[mi], &Bf[ni>>1][(ni&1)*2]);
                if(g==2){
                    u32 Cf[2][4];
#pragma unroll
                    for(int p=0;p<2;p++){
                        int r=rB0+p*16, u=2*s+uB;
                        ldmx4(Cf[p], B2b+(u32)(r*128+((u^(r&7))<<4)));
                    }
#pragma unroll
                    for(int mi=0;mi<2;mi++)
#pragma unroll
                    for(int ni=0;ni<4;ni++)
                        mma16816(accE[mi][ni], Af[mi], &Cf[ni>>1][(ni&1)*2]);
                }
            }
        }
    }
    const int qr=lane>>2, qc=(lane&3)*2;
#pragma unroll
    for(int mi=0;mi<2;mi++)
#pragma unroll
    for(int ni=0;ni<4;ni++){
        int oc=oc0+nw*32+ni*8+qc;
        int b =b0+mw*32+mi*16+qr;
        float cb0=cb[oc], cb1=cb[oc+1], db0=db[oc], db1=db[oc+1];
        const float* D=accD[mi][ni]; const float* E=accE[mi][ni];
        float v00=fmaxf(fmaxf(D[0]+cb0,0.f)+E[0]+db0,0.f);
        float v01=fmaxf(fmaxf(D[1]+cb1,0.f)+E[1]+db1,0.f);
        float v10=fmaxf(fmaxf(D[2]+cb0,0.f)+E[2]+db0,0.f);
        float v11=fmaxf(fmaxf(D[3]+cb1,0.f)+E[3]+db1,0.f);
        if(OUTM==0){
            u32* P=(u32*)g_X2s;
            size_t i0=((size_t)t*BATCH+b)*C1+oc;
            *(ull*)&P[i0] = (ull)packA2(v00) | ((ull)packA2(v01)<<32);
            size_t i1=((size_t)t*BATCH+b+8)*C1+oc;
            *(ull*)&P[i1] = (ull)packA2(v10) | ((ull)packA2(v11)<<32);
        } else {
            g_X3[((size_t)oc*NODES+t)*BATCH+b]=v00;
            g_X3[((size_t)(oc+1)*NODES+t)*BATCH+b]=v01;
            g_X3[((size_t)oc*NODES+t)*BATCH+b+8]=v10;
            g_X3[((size_t)(oc+1)*NODES+t)*BATCH+b+8]=v11;
        }
    }
}
__global__ void __launch_bounds__(256,2)
k_tcn1(const float* __restrict__ cb, const float* __restrict__ db){
    __shared__ __align__(16) char smem[32768];
    tcnT<C0,3,0>(g_X1s, g_W1s, cb, db, smem);
}
__global__ void __launch_bounds__(256,2)
k_tcn2(const float* __restrict__ cb, const float* __restrict__ db){
    __shared__ __align__(16) char smem[32768];
    tcnT<C1,9,1>(g_X2s, g_W2s, cb, db, smem);
}

// ---------- FC + scratch re-zero ----------
#define FC_BM 32
#define FC_BK 32
__global__ void __launch_bounds__(256)
k_fc(const float* __restrict__ W, const float* __restrict__ bias, float* __restrict__ out){
    const float* T=g_X3;
    __shared__ float Ts[FC_BK][FC_BM+1];
    __shared__ float Ws2[80][FC_BK+1];
    int b0=blockIdx.x*FC_BM, tid=threadIdx.x, tr=tid/16, tc=tid%16;
    float acc[2][5]={};
    for(int k0=0;k0<FCIN;k0+=FC_BK){
        for(int i=tid;i<FC_BK*FC_BM;i+=256){
            int k=i/FC_BM, m=i%FC_BM;
            Ts[k][m]=T[(size_t)(k0+k)*BATCH+b0+m];
        }
        for(int i=tid;i<80*FC_BK;i+=256){
            int n=i/FC_BK, k=i%FC_BK;
            Ws2[n][k]=(n<FCOUT)?W[(size_t)n*FCIN+k0+k]:0.f;
        }
        __syncthreads();
#pragma unroll
        for(int kk=0;kk<FC_BK;kk++){
            float a0=Ts[kk][tr*2+0], a1=Ts[kk][tr*2+1];
#pragma unroll
            for(int j=0;j<5;j++){
                float bv=Ws2[tc*5+j][kk];
                acc[0][j]=fmaf(a0,bv,acc[0][j]);
                acc[1][j]=fmaf(a1,bv,acc[1][j]);
            }
        }
        __syncthreads();
    }
#pragma unroll
    for(int i=0;i<2;i++){
        int b=b0+tr*2+i;
#pragma unroll
        for(int j=0;j<5;j++){
            int o=tc*5+j;
            if(o<FCOUT) out[(size_t)b*FCOUT+o]=acc[i][j]+bias[o];
        }
    }
    // re-zero scratch for next invocation (stream-ordered; arrays zero at t=0)
    for(int i=blockIdx.x*256+tid;i<NTOT;i+=gridDim.x*256) g_deg[i]=0.f;
    for(int i=blockIdx.x*256+tid;i<NTOT*INCH;i+=gridDim.x*256) g_A0[i]=0.f;
}

// ---------- launch (tcn1 is launch #4 for ncu) ----------
extern "C" void kernel_launch(void* const* d_in, const int* in_sizes, int n_in,
                              void* d_out, int out_size){
    const float* x=(const float*)d_in[0];
    const int* ei=(const int*)d_in[1];
    const float* gcn_w=(const float*)d_in[2];
    const float* gcn_b=(const float*)d_in[3];
    const float* cw0=(const float*)d_in[4];
    const float* cb0=(const float*)d_in[5];
    const float* dw0=(const float*)d_in[6];
    const float* db0=(const float*)d_in[7];
    const float* cw1=(const float*)d_in[8];
    const float* cb1=(const float*)d_in[9];
    const float* dw1=(const float*)d_in[10];
    const float* db1=(const float*)d_in[11];
    const float* cw2=(const float*)d_in[12];
    const float* cb2=(const float*)d_in[13];
    const float* dw2=(const float*)d_in[14];
    const float* db2=(const float*)d_in[15];
    const float* fc_w=(const float*)d_in[16];
    const float* fc_b=(const float*)d_in[17];
    float* out=(float*)d_out;
    const int* src=ei;
    const int* dst=ei+EDGES;

    k_pre<<<NB_LIN+NB_DEG+NB_WS,256>>>(x,gcn_w,dst,cw1,dw1,cw2,dw2);
    k_scatter<<<NB_LIN+NB_DEG,256>>>(src,dst,gcn_b);
    k_tcn0<<<dim3(NODES,BATCH/128,C0/64),256>>>(cw0,cb0,dw0,db0);
    k_tcn1<<<dim3(NODES,BATCH/128,C1/64),256>>>(cb1,db1);
    k_tcn2<<<dim3(NODES,BATCH/128,C2/64),256>>>(cb2,db2);
    k_fc<<<BATCH/FC_BM,256>>>(fc_w,fc_b,out);
}

// round 15
// speedup vs baseline: 1.8126x; 1.1908x over previous
#include <cuda_runtime.h>
#include <cuda_fp16.h>
#include <cstdint>

#define NTOT 61440
#define NODES 30
#define BATCH 2048
#define INCH 12
#define EDGES 491520
#define C0 128
#define C1 512
#define C2 128
#define FCIN (C2*NODES)
#define FCOUT 72
#define NB_LIN 240
#define NB_DEG 1920
#define NB_WS 2048
#define NB_Z 2880            // zero A0: NTOT*INCH/256
#define NB_NI 2880           // node-init: NTOT*INCH/256
#define NB_ES 23040          // edge scatter: EDGES*INCH/256

typedef unsigned long long ull;
typedef unsigned short u16;
typedef uint32_t u32;
typedef ulonglong2 u128;

__device__ float g_h[NTOT*INCH];
__device__ float g_deg[NTOT];               // zeroed by k_fc tail
__device__ float g_A0[NTOT*INCH];           // zeroed by k_pre segment
__device__ float g_X3[(size_t)C2*NODES*BATCH];                    // [c][t][b]
__device__ __align__(16) ull g_X1s[(size_t)NODES*BATCH*(C0/2)];   // [t][b] swizzled f16-pair rows
__device__ __align__(16) ull g_X2s[(size_t)NODES*BATCH*(C1/2)];
__device__ __align__(16) ull g_W1s[(size_t)C1*4*(C0/2)];          // [oc][g] swizzled (wh,wh) rows
__device__ __align__(16) ull g_W2s[(size_t)C2*4*(C1/2)];

// ---------- helpers ----------
__device__ __forceinline__ ull dup2(float v){ ull r; asm("mov.b64 %0,{%1,%1};":"=l"(r):"f"(v)); return r; }
__device__ __forceinline__ void unpack2(ull v,float&lo,float&hi){ asm("mov.b64 {%0,%1},%2;":"=f"(lo),"=f"(hi):"l"(v)); }
__device__ __forceinline__ void fma2(ull&d,ull a,ull b){ asm("fma.rn.f32x2 %0,%1,%2,%0;":"+l"(d):"l"(a),"l"(b)); }
__device__ __forceinline__ u32 packA2(float v){       // (xh, xl) f16 pair
    __half h=__float2half_rn(v);
    __half l=__float2half_rn(v-__half2float(h));
    return (u32)__half_as_ushort(h) | ((u32)__half_as_ushort(l)<<16);
}
__device__ __forceinline__ u32 packW2(float v){       // (wh, wh)
    __half h=__float2half_rn(v);
    u32 s=__half_as_ushort(h);
    return s|(s<<16);
}
__device__ __forceinline__ void ldmx4(u32* r, u32 addr){
    asm volatile("ldmatrix.sync.aligned.m8n8.x4.shared.b16 {%0,%1,%2,%3}, [%4];"
        :"=r"(r[0]),"=r"(r[1]),"=r"(r[2]),"=r"(r[3]):"r"(addr));
}
__device__ __forceinline__ void mma16816(float* d, const u32* a, const u32* b){
    asm volatile("mma.sync.aligned.m16n8k16.row.col.f32.f16.f16.f32 "
        "{%0,%1,%2,%3},{%4,%5,%6,%7},{%8,%9},{%0,%1,%2,%3};"
        :"+f"(d[0]),"+f"(d[1]),"+f"(d[2]),"+f"(d[3])
        :"r"(a[0]),"r"(a[1]),"r"(a[2]),"r"(a[3]),"r"(b[0]),"r"(b[1]));
}
#define SW(q,r) ((((( (q)>>1)^((r)&7))<<1))|((q)&1))

// ---------- launch 1: GCN linear | degree | weight split (swizzled) | zero A0 ----------
__global__ void k_pre(const float* __restrict__ x, const float* __restrict__ w,
                      const int* __restrict__ dst,
                      const float* __restrict__ cw1, const float* __restrict__ dw1,
                      const float* __restrict__ cw2, const float* __restrict__ dw2){
    int bid=blockIdx.x;
    if(bid<NB_LIN){
        __shared__ float sw[INCH*INCH];
        if(threadIdx.x<INCH*INCH) sw[threadIdx.x]=w[threadIdx.x];
        __syncthreads();
        int n=bid*blockDim.x+threadIdx.x; if(n>=NTOT) return;
        float xr[INCH];
#pragma unroll
        for(int i=0;i<INCH;i++) xr[i]=x[n*INCH+i];
#pragma unroll
        for(int c=0;c<INCH;c++){
            float s=0.f;
#pragma unroll
            for(int i=0;i<INCH;i++) s=fmaf(sw[c*INCH+i],xr[i],s);
            g_h[n*INCH+c]=s;
        }
    } else if(bid<NB_LIN+NB_DEG){
        int e=(bid-NB_LIN)*blockDim.x+threadIdx.x;
        if(e<EDGES) atomicAdd(&g_deg[dst[e]],1.0f);
    } else if(bid<NB_LIN+NB_DEG+NB_WS){
        int i=(bid-NB_LIN-NB_DEG)*256+threadIdx.x;
        if(i<C1*4*C0){
            int oc=i/(4*C0), g=(i/C0)%4, ic=i%C0;
            float v = g<3 ? cw1[(oc*C0+ic)*3+g] : dw1[oc*C0+ic];
            ((u32*)g_W1s)[((size_t)oc*4+g)*C0 + ((ic>>5)*16+SW((ic>>1)&15,oc))*2 + (ic&1)]=packW2(v);
        } else {
            i-=C1*4*C0;
            if(i<C2*4*C1){
                int oc=i/(4*C1), g=(i/C1)%4, ic=i%C1;
                float v = g<3 ? cw2[(oc*C1+ic)*3+g] : dw2[oc*C1+ic];
                ((u32*)g_W2s)[((size_t)oc*4+g)*C1 + ((ic>>5)*16+SW((ic>>1)&15,oc))*2 + (ic&1)]=packW2(v);
            }
        }
    } else {
        int i=(bid-NB_LIN-NB_DEG-NB_WS)*256+threadIdx.x;
        if(i<NTOT*INCH) g_A0[i]=0.f;
    }
}

// ---------- launch 2: node init + edge scatter, (e,c)-parallel atomics ----------
__global__ void k_scatter(const int* __restrict__ src, const int* __restrict__ dst,
                          const float* __restrict__ gcn_b){
    int bid=blockIdx.x;
    if(bid<NB_NI){
        int id=bid*256+threadIdx.x; if(id>=NTOT*INCH) return;
        int n=id/INCH, c=id%INCH;
        float di2=__frcp_rn(g_deg[n]+1.0f);
        atomicAdd(&g_A0[id], fmaf(di2,g_h[id],gcn_b[c]));
    } else {
        int id=(bid-NB_NI)*256+threadIdx.x; if(id>=EDGES*INCH) return;
        int e=id/INCH, c=id%INCH;
        int s=src[e], d=dst[e];
        float sc=rsqrtf(g_deg[s]+1.0f)*rsqrtf(g_deg[d]+1.0f);
        atomicAdd(&g_A0[d*INCH+c], sc*g_h[s*INCH+c]);
    }
}

// ---------- launch 3: tcn0 scalar (12->128), emits swizzled f16-pair stream ----------
__global__ void __launch_bounds__(256,2)
k_tcn0(const float* __restrict__ cw, const float* __restrict__ cb,
       const float* __restrict__ dw, const float* __restrict__ db){
    constexpr int IN=INCH, BN=128, BM=64, NT=256, BK=12;
    __shared__ __align__(16) char smem[43008];
    float* A_s=(float*)smem;                 // 18432
    float* B_s=(float*)(smem+18432);         // 24576
    const int t=blockIdx.x, b0=blockIdx.y*BN, oc0=blockIdx.z*BM;
    const int tid=threadIdx.x, tx=tid&31, ty=tid>>5;
    const int bb=tx*4, oct=ty*8;
    ull acc1[8][2], acc2[8][2];
#pragma unroll
    for(int j=0;j<8;j++){acc1[j][0]=acc1[j][1]=acc2[j][0]=acc2[j][1]=0ULL;}
    for(int i=tid;i<BK*3*BN;i+=NT){
        int ic=i/(3*BN), r=i%(3*BN), kk=r/BN, b=r%BN;
        int tk=t+(kk-2);
        A_s[i]=(tk>=0)?g_A0[((size_t)(b0+b)*NODES+tk)*IN+ic]:0.f;
    }
    for(int i=tid;i<BM*BK*4;i+=NT){
        int oc=i/(BK*4), r=i%(BK*4), ic=r/4, w=r&3;
        float v=(w<3)?cw[((size_t)(oc0+oc)*IN+ic)*3+w]:dw[(size_t)(oc0+oc)*IN+ic];
        *reinterpret_cast<ull*>(&B_s[i*2])=dup2(v);
    }
    __syncthreads();
#pragma unroll
    for(int ic=0;ic<BK;ic++){
        ulonglong2 a0=*reinterpret_cast<const ulonglong2*>(&A_s[(ic*3+0)*BN+bb]);
        ulonglong2 a1=*reinterpret_cast<const ulonglong2*>(&A_s[(ic*3+1)*BN+bb]);
        ulonglong2 a2=*reinterpret_cast<const ulonglong2*>(&A_s[(ic*3+2)*BN+bb]);
#pragma unroll
        for(int j=0;j<8;j++){
            const float* wb=&B_s[((oct+j)*BK+ic)*8];
            ulonglong2 wA=*reinterpret_cast<const ulonglong2*>(wb);
            ulonglong2 wB=*reinterpret_cast<const ulonglong2*>(wb+4);
            fma2(acc1[j][0],wA.x,a0.x); fma2(acc1[j][1],wA.x,a0.y);
            fma2(acc1[j][0],wA.y,a1.x); fma2(acc1[j][1],wA.y,a1.y);
            fma2(acc1[j][0],wB.x,a2.x); fma2(acc1[j][1],wB.x,a2.y);
            fma2(acc2[j][0],wB.y,a2.x); fma2(acc2[j][1],wB.y,a2.y);
        }
    }
    u32* P=(u32*)g_X1s;
#pragma unroll
    for(int j=0;j<8;j++){
        int oc=oc0+oct+j;
        float cbv=cb[oc], dbv=db[oc];
        float c0,c1,c2,c3,d0,d1,d2,d3;
        unpack2(acc1[j][0],c0,c1); unpack2(acc1[j][1],c2,c3);
        unpack2(acc2[j][0],d0,d1); unpack2(acc2[j][1],d2,d3);
        float o[4]={fmaxf(fmaxf(c0+cbv,0.f)+d0+dbv,0.f), fmaxf(fmaxf(c1+cbv,0.f)+d1+dbv,0.f),
                    fmaxf(fmaxf(c2+cbv,0.f)+d2+dbv,0.f), fmaxf(fmaxf(c3+cbv,0.f)+d3+dbv,0.f)};
#pragma unroll
        for(int i=0;i<4;i++){
            int b=b0+bb+i;
            P[((size_t)t*BATCH+b)*C0 + ((oc>>5)*16+SW((oc>>1)&15,b))*2 + (oc&1)]=packA2(o[i]);
        }
    }
}

// ---------- tensor TCN: pre-swizzled streams, identity 16B staging ----------
template<int IN,int DIL,int OUTM>
__device__ __forceinline__ void tcnT(const ull* __restrict__ Xs, const ull* __restrict__ Ws,
      const float* __restrict__ cb, const float* __restrict__ db, char* smem){
    constexpr int RW=IN/2, RW2=RW/2, CH=RW/16;
    ull* A_s=(ull*)smem;                     // 16KB
    ull* B_s=(ull*)(smem+16384);             // 8KB
    ull* B2_s=(ull*)(smem+24576);            // 8KB
    const int t=blockIdx.x, b0=blockIdx.y*128, oc0=blockIdx.z*64;
    const int tid=threadIdx.x, lane=tid&31, w=tid>>5;
    const int mw=w&3, nw=w>>2;
    const u32 Ab=(u32)__cvta_generic_to_shared(A_s);
    const u32 Bb=(u32)__cvta_generic_to_shared(B_s);
    const u32 B2b=(u32)__cvta_generic_to_shared(B2_s);
    const int sub=lane>>3, l7=lane&7;
    const int rA0=mw*32+l7+((sub&1)<<3);
    const int rB0=nw*32+l7+((sub>>1)<<3);
    const int uA=sub>>1, uB=sub&1;
    const u128* Xv=(const u128*)Xs;
    const u128* Wv=(const u128*)Ws;
    float accD[2][4][4]={}, accE[2][4][4]={};
#pragma unroll 1
    for(int g=0;g<3;g++){
        const int tk=t-(2-g)*DIL;
#pragma unroll 1
        for(int kc=0;kc<CH;kc++){
            __syncthreads();
#pragma unroll
            for(int i=tid;i<1024;i+=256){          // A: 128 rows x 8 u128, identity copy
                int b=i>>3, jj=i&7;
                u128 v; v.x=0ULL; v.y=0ULL;
                if(tk>=0) v=Xv[((size_t)tk*BATCH+b0+b)*RW2+kc*8+jj];
                ((u128*)A_s)[i]=v;
            }
#pragma unroll
            for(int i=tid;i<512;i+=256){           // B: 64 rows x 8 u128
                int n=i>>3, jj=i&7;
                ((u128*)B_s)[i]=Wv[((size_t)(oc0+n)*4+g)*RW2+kc*8+jj];
            }
            if(g==2)
#pragma unroll
            for(int i=tid;i<512;i+=256){
                int n=i>>3, jj=i&7;
                ((u128*)B2_s)[i]=Wv[((size_t)(oc0+n)*4+3)*RW2+kc*8+jj];
            }
            __syncthreads();
#pragma unroll
            for(int s=0;s<4;s++){
                u32 Af[2][4], Bf[2][4];
#pragma unroll
                for(int mi=0;mi<2;mi++){
                    int r=rA0+mi*16, u=2*s+uA;
                    ldmx4(Af[mi], Ab+(u32)(r*128+((u^(r&7))<<4)));
                }
#pragma unroll
                for(int p=0;p<2;p++){
                    int r=rB0+p*16, u=2*s+uB;
                    ldmx4(Bf[p], Bb+(u32)(r*128+((u^(r&7))<<4)));
                }
#pragma unroll
                for(int mi=0;mi<2;mi++)
#pragma unroll
                for(int ni=0;ni<4;ni++)
                    mma16816(accD[mi][ni], Af[mi], &Bf[ni>>1][(ni&1)*2]);
                if(g==2){
                    u32 Cf[2][4];
#pragma unroll
                    for(int p=0;p<2;p++){
                        int r=rB0+p*16, u=2*s+uB;
                        ldmx4(Cf[p], B2b+(u32)(r*128+((u^(r&7))<<4)));
                    }
#pragma unroll
                    for(int mi=0;mi<2;mi++)
#pragma unroll
                    for(int ni=0;ni<4;ni++)
                        mma16816(accE[mi][ni], Af[mi], &Cf[ni>>1][(ni&1)*2]);
                }
            }
        }
    }
    const int qr=lane>>2, qc=(lane&3)*2;
#pragma unroll
    for(int mi=0;mi<2;mi++)
#pragma unroll
    for(int ni=0;ni<4;ni++){
        int oc=oc0+nw*32+ni*8+qc;
        int b =b0+mw*32+mi*16+qr;
        float cb0=cb[oc], cb1=cb[oc+1], db0=db[oc], db1=db[oc+1];
        const float* D=accD[mi][ni]; const float* E=accE[mi][ni];
        float v00=fmaxf(fmaxf(D[0]+cb0,0.f)+E[0]+db0,0.f);
        float v01=fmaxf(fmaxf(D[1]+cb1,0.f)+E[1]+db1,0.f);
        float v10=fmaxf(fmaxf(D[2]+cb0,0.f)+E[2]+db0,0.f);
        float v11=fmaxf(fmaxf(D[3]+cb1,0.f)+E[3]+db1,0.f);
        if(OUTM==0){
            int qu=oc>>1, kc=qu>>4, q=qu&15;    // oc even: one ull per pair
            g_X2s[((size_t)t*BATCH+b)*(C1/2)+kc*16+SW(q,b)]
                = (ull)packA2(v00) | ((ull)packA2(v01)<<32);
            g_X2s[((size_t)t*BATCH+b+8)*(C1/2)+kc*16+SW(q,b+8)]
                = (ull)packA2(v10) | ((ull)packA2(v11)<<32);
        } else {
            g_X3[((size_t)oc*NODES+t)*BATCH+b]=v00;
            g_X3[((size_t)(oc+1)*NODES+t)*BATCH+b]=v01;
            g_X3[((size_t)oc*NODES+t)*BATCH+b+8]=v10;
            g_X3[((size_t)(oc+1)*NODES+t)*BATCH+b+8]=v11;
        }
    }
}
__global__ void __launch_bounds__(256,2)
k_tcn1(const float* __restrict__ cb, const float* __restrict__ db){
    __shared__ __align__(16) char smem[32768];
    tcnT<C0,3,0>(g_X1s, g_W1s, cb, db, smem);
}
__global__ void __launch_bounds__(256,2)
k_tcn2(const float* __restrict__ cb, const float* __restrict__ db){
    __shared__ __align__(16) char smem[32768];
    tcnT<C1,9,1>(g_X2s, g_W2s, cb, db, smem);
}

// ---------- FC + deg re-zero ----------
#define FC_BM 32
#define FC_BK 32
__global__ void __launch_bounds__(256)
k_fc(const float* __restrict__ W, const float* __restrict__ bias, float* __restrict__ out){
    const float* T=g_X3;
    __shared__ float Ts[FC_BK][FC_BM+1];
    __shared__ float Ws2[80][FC_BK+1];
    int b0=blockIdx.x*FC_BM, tid=threadIdx.x, tr=tid/16, tc=tid%16;
    float acc[2][5]={};
    for(int k0=0;k0<FCIN;k0+=FC_BK){
        for(int i=tid;i<FC_BK*FC_BM;i+=256){
            int k=i/FC_BM, m=i%FC_BM;
            Ts[k][m]=T[(size_t)(k0+k)*BATCH+b0+m];
        }
        for(int i=tid;i<80*FC_BK;i+=256){
            int n=i/FC_BK, k=i%FC_BK;
            Ws2[n][k]=(n<FCOUT)?W[(size_t)n*FCIN+k0+k]:0.f;
        }
        __syncthreads();
#pragma unroll
        for(int kk=0;kk<FC_BK;kk++){
            float a0=Ts[kk][tr*2+0], a1=Ts[kk][tr*2+1];
#pragma unroll
            for(int j=0;j<5;j++){
                float bv=Ws2[tc*5+j][kk];
                acc[0][j]=fmaf(a0,bv,acc[0][j]);
                acc[1][j]=fmaf(a1,bv,acc[1][j]);
            }
        }
        __syncthreads();
    }
#pragma unroll
    for(int i=0;i<2;i++){
        int b=b0+tr*2+i;
#pragma unroll
        for(int j=0;j<5;j++){
            int o=tc*5+j;
            if(o<FCOUT) out[(size_t)b*FCOUT+o]=acc[i][j]+bias[o];
        }
    }
    for(int i=blockIdx.x*256+tid;i<NTOT;i+=gridDim.x*256) g_deg[i]=0.f;
}

// ---------- launch (tcn1 is launch #4 for ncu) ----------
extern "C" void kernel_launch(void* const* d_in, const int* in_sizes, int n_in,
                              void* d_out, int out_size){
    const float* x=(const float*)d_in[0];
    const int* ei=(const int*)d_in[1];
    const float* gcn_w=(const float*)d_in[2];
    const float* gcn_b=(const float*)d_in[3];
    const float* cw0=(const float*)d_in[4];
    const float* cb0=(const float*)d_in[5];
    const float* dw0=(const float*)d_in[6];
    const float* db0=(const float*)d_in[7];
    const float* cw1=(const float*)d_in[8];
    const float* cb1=(const float*)d_in[9];
    const float* dw1=(const float*)d_in[10];
    const float* db1=(const float*)d_in[11];
    const float* cw2=(const float*)d_in[12];
    const float* cb2=(const float*)d_in[13];
    const float* dw2=(const float*)d_in[14];
    const float* db2=(const float*)d_in[15];
    const float* fc_w=(const float*)d_in[16];
    const float* fc_b=(const float*)d_in[17];
    float* out=(float*)d_out;
    const int* src=ei;
    const int* dst=ei+EDGES;

    k_pre<<<NB_LIN+NB_DEG+NB_WS+NB_Z,256>>>(x,gcn_w,dst,cw1,dw1,cw2,dw2);
    k_scatter<<<NB_NI+NB_ES,256>>>(src,dst,gcn_b);
    k_tcn0<<<dim3(NODES,BATCH/128,C0/64),256>>>(cw0,cb0,dw0,db0);
    k_tcn1<<<dim3(NODES,BATCH/128,C1/64),256>>>(cb1,db1);
    k_tcn2<<<dim3(NODES,BATCH/128,C2/64),256>>>(cb2,db2);
    k_fc<<<BATCH/FC_BM,256>>>(fc_w,fc_b,out);
}

// round 16
// speedup vs baseline: 2.4304x; 1.3408x over previous
#include <cuda_runtime.h>
#include <cuda_fp16.h>
#include <cstdint>

#define NTOT 61440
#define NODES 30
#define BATCH 2048
#define INCH 12
#define EDGES 491520
#define C0 128
#define C1 512
#define C2 128
#define FCIN (C2*NODES)
#define FCOUT 72
#define NB_LIN 240
#define NB_DEG 1920
#define NB_WS 2048
#define NB_Z 2880
#define NB_NI 2880
#define NB_ES 23040

typedef unsigned long long ull;
typedef unsigned short u16;
typedef uint32_t u32;
typedef ulonglong2 u128;

__device__ float g_h[NTOT*INCH];
__device__ float g_deg[NTOT];               // zeroed by k_fc tail
__device__ float g_A0[NTOT*INCH];           // zeroed by k_pre segment
__device__ float g_X3[(size_t)C2*NODES*BATCH];                    // [c][t][b]
__device__ __align__(16) ull g_X1s[(size_t)NODES*BATCH*(C0/2)];   // [t][b] swizzled f16-pair rows
__device__ __align__(16) ull g_X2s[(size_t)NODES*BATCH*(C1/2)];
__device__ __align__(16) ull g_W1s[(size_t)C1*4*(C0/2)];          // [oc][g] swizzled (wh,wh) rows
__device__ __align__(16) ull g_W2s[(size_t)C2*4*(C1/2)];

// ---------- helpers ----------
__device__ __forceinline__ ull dup2(float v){ ull r; asm("mov.b64 %0,{%1,%1};":"=l"(r):"f"(v)); return r; }
__device__ __forceinline__ void unpack2(ull v,float&lo,float&hi){ asm("mov.b64 {%0,%1},%2;":"=f"(lo),"=f"(hi):"l"(v)); }
__device__ __forceinline__ void fma2(ull&d,ull a,ull b){ asm("fma.rn.f32x2 %0,%1,%2,%0;":"+l"(d):"l"(a),"l"(b)); }
__device__ __forceinline__ u32 packA2(float v){
    __half h=__float2half_rn(v);
    __half l=__float2half_rn(v-__half2float(h));
    return (u32)__half_as_ushort(h) | ((u32)__half_as_ushort(l)<<16);
}
__device__ __forceinline__ u32 packW2(float v){
    __half h=__float2half_rn(v);
    u32 s=__half_as_ushort(h);
    return s|(s<<16);
}
__device__ __forceinline__ void ldmx4(u32* r, u32 addr){
    asm volatile("ldmatrix.sync.aligned.m8n8.x4.shared.b16 {%0,%1,%2,%3}, [%4];"
        :"=r"(r[0]),"=r"(r[1]),"=r"(r[2]),"=r"(r[3]):"r"(addr));
}
__device__ __forceinline__ void mma16816(float* d, const u32* a, const u32* b){
    asm volatile("mma.sync.aligned.m16n8k16.row.col.f32.f16.f16.f32 "
        "{%0,%1,%2,%3},{%4,%5,%6,%7},{%8,%9},{%0,%1,%2,%3};"
        :"+f"(d[0]),"+f"(d[1]),"+f"(d[2]),"+f"(d[3])
        :"r"(a[0]),"r"(a[1]),"r"(a[2]),"r"(a[3]),"r"(b[0]),"r"(b[1]));
}
__device__ __forceinline__ void cpasync16(u32 sm, const void* g){
    asm volatile("cp.async.cg.shared.global [%0],[%1],16;"::"r"(sm),"l"(g):"memory");
}
#define CP_COMMIT() asm volatile("cp.async.commit_group;":::"memory")
#define CP_WAIT1()  asm volatile("cp.async.wait_group 1;":::"memory")
#define CP_WAIT0()  asm volatile("cp.async.wait_group 0;":::"memory")
#define SW(q,r) ((((( (q)>>1)^((r)&7))<<1))|((q)&1))

// ---------- launch 1: GCN linear | degree | weight split (swizzled) | zero A0 ----------
__global__ void k_pre(const float* __restrict__ x, const float* __restrict__ w,
                      const int* __restrict__ dst,
                      const float* __restrict__ cw1, const float* __restrict__ dw1,
                      const float* __restrict__ cw2, const float* __restrict__ dw2){
    int bid=blockIdx.x;
    if(bid<NB_LIN){
        __shared__ float sw[INCH*INCH];
        if(threadIdx.x<INCH*INCH) sw[threadIdx.x]=w[threadIdx.x];
        __syncthreads();
        int n=bid*blockDim.x+threadIdx.x; if(n>=NTOT) return;
        float xr[INCH];
#pragma unroll
        for(int i=0;i<INCH;i++) xr[i]=x[n*INCH+i];
#pragma unroll
        for(int c=0;c<INCH;c++){
            float s=0.f;
#pragma unroll
            for(int i=0;i<INCH;i++) s=fmaf(sw[c*INCH+i],xr[i],s);
            g_h[n*INCH+c]=s;
        }
    } else if(bid<NB_LIN+NB_DEG){
        int e=(bid-NB_LIN)*blockDim.x+threadIdx.x;
        if(e<EDGES) atomicAdd(&g_deg[dst[e]],1.0f);
    } else if(bid<NB_LIN+NB_DEG+NB_WS){
        int i=(bid-NB_LIN-NB_DEG)*256+threadIdx.x;
        if(i<C1*4*C0){
            int oc=i/(4*C0), g=(i/C0)%4, ic=i%C0;
            float v = g<3 ? cw1[(oc*C0+ic)*3+g] : dw1[oc*C0+ic];
            ((u32*)g_W1s)[((size_t)oc*4+g)*C0 + ((ic>>5)*16+SW((ic>>1)&15,oc))*2 + (ic&1)]=packW2(v);
        } else {
            i-=C1*4*C0;
            if(i<C2*4*C1){
                int oc=i/(4*C1), g=(i/C1)%4, ic=i%C1;
                float v = g<3 ? cw2[(oc*C1+ic)*3+g] : dw2[oc*C1+ic];
                ((u32*)g_W2s)[((size_t)oc*4+g)*C1 + ((ic>>5)*16+SW((ic>>1)&15,oc))*2 + (ic&1)]=packW2(v);
            }
        }
    } else {
        int i=(bid-NB_LIN-NB_DEG-NB_WS)*256+threadIdx.x;
        if(i<NTOT*INCH) g_A0[i]=0.f;
    }
}

// ---------- launch 2: node init + edge scatter, (e,c)-parallel atomics ----------
__global__ void k_scatter(const int* __restrict__ src, const int* __restrict__ dst,
                          const float* __restrict__ gcn_b){
    int bid=blockIdx.x;
    if(bid<NB_NI){
        int id=bid*256+threadIdx.x; if(id>=NTOT*INCH) return;
        int n=id/INCH, c=id%INCH;
        float di2=__frcp_rn(g_deg[n]+1.0f);
        atomicAdd(&g_A0[id], fmaf(di2,g_h[id],gcn_b[c]));
    } else {
        int id=(bid-NB_NI)*256+threadIdx.x; if(id>=EDGES*INCH) return;
        int e=id/INCH, c=id%INCH;
        int s=src[e], d=dst[e];
        float sc=rsqrtf(g_deg[s]+1.0f)*rsqrtf(g_deg[d]+1.0f);
        atomicAdd(&g_A0[d*INCH+c], sc*g_h[s*INCH+c]);
    }
}

// ---------- launch 3: tcn0 scalar (12->128), emits swizzled f16-pair stream ----------
__global__ void __launch_bounds__(256,2)
k_tcn0(const float* __restrict__ cw, const float* __restrict__ cb,
       const float* __restrict__ dw, const float* __restrict__ db){
    constexpr int IN=INCH, BN=128, BM=64, NT=256, BK=12;
    __shared__ __align__(16) char smem[43008];
    float* A_s=(float*)smem;
    float* B_s=(float*)(smem+18432);
    const int t=blockIdx.x, b0=blockIdx.y*BN, oc0=blockIdx.z*BM;
    const int tid=threadIdx.x, tx=tid&31, ty=tid>>5;
    const int bb=tx*4, oct=ty*8;
    ull acc1[8][2], acc2[8][2];
#pragma unroll
    for(int j=0;j<8;j++){acc1[j][0]=acc1[j][1]=acc2[j][0]=acc2[j][1]=0ULL;}
    for(int i=tid;i<BK*3*BN;i+=NT){
        int ic=i/(3*BN), r=i%(3*BN), kk=r/BN, b=r%BN;
        int tk=t+(kk-2);
        A_s[i]=(tk>=0)?g_A0[((size_t)(b0+b)*NODES+tk)*IN+ic]:0.f;
    }
    for(int i=tid;i<BM*BK*4;i+=NT){
        int oc=i/(BK*4), r=i%(BK*4), ic=r/4, w=r&3;
        float v=(w<3)?cw[((size_t)(oc0+oc)*IN+ic)*3+w]:dw[(size_t)(oc0+oc)*IN+ic];
        *reinterpret_cast<ull*>(&B_s[i*2])=dup2(v);
    }
    __syncthreads();
#pragma unroll
    for(int ic=0;ic<BK;ic++){
        ulonglong2 a0=*reinterpret_cast<const ulonglong2*>(&A_s[(ic*3+0)*BN+bb]);
        ulonglong2 a1=*reinterpret_cast<const ulonglong2*>(&A_s[(ic*3+1)*BN+bb]);
        ulonglong2 a2=*reinterpret_cast<const ulonglong2*>(&A_s[(ic*3+2)*BN+bb]);
#pragma unroll
        for(int j=0;j<8;j++){
            const float* wb=&B_s[((oct+j)*BK+ic)*8];
            ulonglong2 wA=*reinterpret_cast<const ulonglong2*>(wb);
            ulonglong2 wB=*reinterpret_cast<const ulonglong2*>(wb+4);
            fma2(acc1[j][0],wA.x,a0.x); fma2(acc1[j][1],wA.x,a0.y);
            fma2(acc1[j][0],wA.y,a1.x); fma2(acc1[j][1],wA.y,a1.y);
            fma2(acc1[j][0],wB.x,a2.x); fma2(acc1[j][1],wB.x,a2.y);
            fma2(acc2[j][0],wB.y,a2.x); fma2(acc2[j][1],wB.y,a2.y);
        }
    }
    u32* P=(u32*)g_X1s;
#pragma unroll
    for(int j=0;j<8;j++){
        int oc=oc0+oct+j;
        float cbv=cb[oc], dbv=db[oc];
        float c0,c1,c2,c3,d0,d1,d2,d3;
        unpack2(acc1[j][0],c0,c1); unpack2(acc1[j][1],c2,c3);
        unpack2(acc2[j][0],d0,d1); unpack2(acc2[j][1],d2,d3);
        float o[4]={fmaxf(fmaxf(c0+cbv,0.f)+d0+dbv,0.f), fmaxf(fmaxf(c1+cbv,0.f)+d1+dbv,0.f),
                    fmaxf(fmaxf(c2+cbv,0.f)+d2+dbv,0.f), fmaxf(fmaxf(c3+cbv,0.f)+d3+dbv,0.f)};
#pragma unroll
        for(int i=0;i<4;i++){
            int b=b0+bb+i;
            P[((size_t)t*BATCH+b)*C0 + ((oc>>5)*16+SW((oc>>1)&15,b))*2 + (oc&1)]=packA2(o[i]);
        }
    }
}

// ---------- tensor TCN: M=64 x N=128 tiles, double-buffered cp.async, 4 uniform passes ----------
template<int IN,int DIL,int OUTM>
__device__ __forceinline__ void tcnT(const ull* __restrict__ Xs, const ull* __restrict__ Ws,
      const float* __restrict__ cb, const float* __restrict__ db, char* smem){
    constexpr int RW2=IN/4;          // u128 per row
    constexpr int CH=RW2/8;          // chunks per pass (8 u128 = 128B per row-chunk)
    constexpr int NCH=4*CH;
    // buffers: A[2] 8KB @0,8192 ; B[2] 16KB @16384,32768
    const int t=blockIdx.x, b0=blockIdx.y*64, oc0=blockIdx.z*128;
    const int tid=threadIdx.x, lane=tid&31, w=tid>>5;
    const int mw=w&1, nw=w>>1;       // 2 x 4 warp grid, warp tile 32x32
    const u32 Sb=(u32)__cvta_generic_to_shared(smem);
    const int sub=lane>>3, l7=lane&7;
    const int rA0=mw*32+l7+((sub&1)<<3);
    const int rB0=nw*32+l7+((sub>>1)<<3);
    const int uA=sub>>1, uB=sub&1;
    const u128* Xv=(const u128*)Xs;
    const u128* Wv=(const u128*)Ws;
    float accD[2][4][4]={}, accE[2][4][4]={};

    auto stage=[&](int j,int buf){
        int g=j/CH, kc=j-g*CH;
        int tk=(g<3)? t-(2-g)*DIL : t;
        u32 aB=Sb+buf*8192, bB=Sb+16384+buf*16384;
        if(tk>=0){
#pragma unroll
            for(int i=tid;i<512;i+=256)
                cpasync16(aB+i*16, &Xv[((size_t)tk*BATCH+b0+(i>>3))*RW2+kc*8+(i&7)]);
        } else {
            u128 z; z.x=0ULL; z.y=0ULL;
#pragma unroll
            for(int i=tid;i<512;i+=256)
                ((u128*)(smem+buf*8192))[i]=z;
        }
#pragma unroll
        for(int i=tid;i<1024;i+=256)
            cpasync16(bB+i*16, &Wv[((size_t)(oc0+(i>>3))*4+g)*RW2+kc*8+(i&7)]);
        CP_COMMIT();
    };

    stage(0,0);
    for(int j=0;j<NCH;j++){
        int buf=j&1;
        if(j+1<NCH){ stage(j+1,1-buf); CP_WAIT1(); }
        else CP_WAIT0();
        __syncthreads();
        const u32 aB=Sb+buf*8192, bB=Sb+16384+buf*16384;
        int g=j/CH;
#pragma unroll
        for(int s=0;s<4;s++){
            u32 Af[2][4], Bf[2][4];
#pragma unroll
            for(int mi=0;mi<2;mi++){
                int r=rA0+mi*16, u=2*s+uA;
                ldmx4(Af[mi], aB+(u32)(r*128+((u^(r&7))<<4)));
            }
#pragma unroll
            for(int p=0;p<2;p++){
                int r=rB0+p*16, u=2*s+uB;
                ldmx4(Bf[p], bB+(u32)(r*128+((u^(r&7))<<4)));
            }
            if(g<3){
#pragma unroll
                for(int mi=0;mi<2;mi++)
#pragma unroll
                for(int ni=0;ni<4;ni++)
                    mma16816(accD[mi][ni], Af[mi], &Bf[ni>>1][(ni&1)*2]);
            } else {
#pragma unroll
                for(int mi=0;mi<2;mi++)
#pragma unroll
                for(int ni=0;ni<4;ni++)
                    mma16816(accE[mi][ni], Af[mi], &Bf[ni>>1][(ni&1)*2]);
            }
        }
        __syncthreads();
    }
    const int qr=lane>>2, qc=(lane&3)*2;
#pragma unroll
    for(int mi=0;mi<2;mi++)
#pragma unroll
    for(int ni=0;ni<4;ni++){
        int oc=oc0+nw*32+ni*8+qc;
        int b =b0+mw*32+mi*16+qr;
        float cb0=cb[oc], cb1=cb[oc+1], db0=db[oc], db1=db[oc+1];
        const float* D=accD[mi][ni]; const float* E=accE[mi][ni];
        float v00=fmaxf(fmaxf(D[0]+cb0,0.f)+E[0]+db0,0.f);
        float v01=fmaxf(fmaxf(D[1]+cb1,0.f)+E[1]+db1,0.f);
        float v10=fmaxf(fmaxf(D[2]+cb0,0.f)+E[2]+db0,0.f);
        float v11=fmaxf(fmaxf(D[3]+cb1,0.f)+E[3]+db1,0.f);
        if(OUTM==0){
            int qu=oc>>1, kc=qu>>4, q=qu&15;
            g_X2s[((size_t)t*BATCH+b)*(C1/2)+kc*16+SW(q,b)]
                = (ull)packA2(v00) | ((ull)packA2(v01)<<32);
            g_X2s[((size_t)t*BATCH+b+8)*(C1/2)+kc*16+SW(q,b+8)]
                = (ull)packA2(v10) | ((ull)packA2(v11)<<32);
        } else {
            g_X3[((size_t)oc*NODES+t)*BATCH+b]=v00;
            g_X3[((size_t)(oc+1)*NODES+t)*BATCH+b]=v01;
            g_X3[((size_t)oc*NODES+t)*BATCH+b+8]=v10;
            g_X3[((size_t)(oc+1)*NODES+t)*BATCH+b+8]=v11;
        }
    }
}
__global__ void __launch_bounds__(256,2)
k_tcn1(const float* __restrict__ cb, const float* __restrict__ db){
    __shared__ __align__(16) char smem[49152];
    tcnT<C0,3,0>(g_X1s, g_W1s, cb, db, smem);
}
__global__ void __launch_bounds__(256,2)
k_tcn2(const float* __restrict__ cb, const float* __restrict__ db){
    __shared__ __align__(16) char smem[49152];
    tcnT<C1,9,1>(g_X2s, g_W2s, cb, db, smem);
}

// ---------- FC + deg re-zero ----------
#define FC_BM 32
#define FC_BK 32
__global__ void __launch_bounds__(256)
k_fc(const float* __restrict__ W, const float* __restrict__ bias, float* __restrict__ out){
    const float* T=g_X3;
    __shared__ float Ts[FC_BK][FC_BM+1];
    __shared__ float Ws2[80][FC_BK+1];
    int b0=blockIdx.x*FC_BM, tid=threadIdx.x, tr=tid/16, tc=tid%16;
    float acc[2][5]={};
    for(int k0=0;k0<FCIN;k0+=FC_BK){
        for(int i=tid;i<FC_BK*FC_BM;i+=256){
            int k=i/FC_BM, m=i%FC_BM;
            Ts[k][m]=T[(size_t)(k0+k)*BATCH+b0+m];
        }
        for(int i=tid;i<80*FC_BK;i+=256){
            int n=i/FC_BK, k=i%FC_BK;
            Ws2[n][k]=(n<FCOUT)?W[(size_t)n*FCIN+k0+k]:0.f;
        }
        __syncthreads();
#pragma unroll
        for(int kk=0;kk<FC_BK;kk++){
            float a0=Ts[kk][tr*2+0], a1=Ts[kk][tr*2+1];
#pragma unroll
            for(int j=0;j<5;j++){
                float bv=Ws2[tc*5+j][kk];
                acc[0][j]=fmaf(a0,bv,acc[0][j]);
                acc[1][j]=fmaf(a1,bv,acc[1][j]);
            }
        }
        __syncthreads();
    }
#pragma unroll
    for(int i=0;i<2;i++){
        int b=b0+tr*2+i;
#pragma unroll
        for(int j=0;j<5;j++){
            int o=tc*5+j;
            if(o<FCOUT) out[(size_t)b*FCOUT+o]=acc[i][j]+bias[o];
        }
    }
    for(int i=blockIdx.x*256+tid;i<NTOT;i+=gridDim.x*256) g_deg[i]=0.f;
}

// ---------- launch (tcn1 is launch #4 for ncu) ----------
extern "C" void kernel_launch(void* const* d_in, const int* in_sizes, int n_in,
                              void* d_out, int out_size){
    const float* x=(const float*)d_in[0];
    const int* ei=(const int*)d_in[1];
    const float* gcn_w=(const float*)d_in[2];
    const float* gcn_b=(const float*)d_in[3];
    const float* cw0=(const float*)d_in[4];
    const float* cb0=(const float*)d_in[5];
    const float* dw0=(const float*)d_in[6];
    const float* db0=(const float*)d_in[7];
    const float* cw1=(const float*)d_in[8];
    const float* cb1=(const float*)d_in[9];
    const float* dw1=(const float*)d_in[10];
    const float* db1=(const float*)d_in[11];
    const float* cw2=(const float*)d_in[12];
    const float* cb2=(const float*)d_in[13];
    const float* dw2=(const float*)d_in[14];
    const float* db2=(const float*)d_in[15];
    const float* fc_w=(const float*)d_in[16];
    const float* fc_b=(const float*)d_in[17];
    float* out=(float*)d_out;
    const int* src=ei;
    const int* dst=ei+EDGES;

    k_pre<<<NB_LIN+NB_DEG+NB_WS+NB_Z,256>>>(x,gcn_w,dst,cw1,dw1,cw2,dw2);
    k_scatter<<<NB_NI+NB_ES,256>>>(src,dst,gcn_b);
    k_tcn0<<<dim3(NODES,BATCH/128,C0/64),256>>>(cw0,cb0,dw0,db0);
    k_tcn1<<<dim3(NODES,BATCH/64,C1/128),256>>>(cb1,db1);
    k_tcn2<<<dim3(NODES,BATCH/64,C2/128),256>>>(cb2,db2);
    k_fc<<<BATCH/FC_BM,256>>>(fc_w,fc_b,out);
}

// round 17
// speedup vs baseline: 2.7478x; 1.1306x over previous
#include <cuda_runtime.h>
#include <cuda_fp16.h>
#include <cstdint>

#define NTOT 61440
#define NODES 30
#define BATCH 2048
#define INCH 12
#define EDGES 491520
#define C0 128
#define C1 512
#define C2 128
#define FCIN (C2*NODES)
#define FCOUT 72
#define NB_LIN 240
#define NB_DEG 1920
#define NB_WS 2048
#define NB_Z 2880
#define NB_WT 1080           // fc_w transpose: FCOUT*FCIN/256
#define NB_NI 2880
#define NB_ES 23040

typedef unsigned long long ull;
typedef unsigned short u16;
typedef uint32_t u32;
typedef ulonglong2 u128;

__device__ float g_h[NTOT*INCH];
__device__ float g_deg[NTOT];               // zeroed by k_fc tail
__device__ float g_A0[NTOT*INCH];           // zeroed by k_pre segment
__device__ float g_X3[(size_t)NODES*BATCH*C2];                    // [t][b][c]
__device__ float g_Wfc[(size_t)FCOUT*FCIN];                       // [o][t*C2+c]
__device__ __align__(16) ull g_X1s[(size_t)NODES*BATCH*(C0/2)];   // [t][b] swizzled f16-pair rows
__device__ __align__(16) ull g_X2s[(size_t)NODES*BATCH*(C1/2)];
__device__ __align__(16) ull g_W1s[(size_t)C1*4*(C0/2)];          // [oc][g] swizzled (wh,wh) rows
__device__ __align__(16) ull g_W2s[(size_t)C2*4*(C1/2)];

// ---------- helpers ----------
__device__ __forceinline__ ull dup2(float v){ ull r; asm("mov.b64 %0,{%1,%1};":"=l"(r):"f"(v)); return r; }
__device__ __forceinline__ void unpack2(ull v,float&lo,float&hi){ asm("mov.b64 {%0,%1},%2;":"=f"(lo),"=f"(hi):"l"(v)); }
__device__ __forceinline__ void fma2(ull&d,ull a,ull b){ asm("fma.rn.f32x2 %0,%1,%2,%0;":"+l"(d):"l"(a),"l"(b)); }
__device__ __forceinline__ u32 packA2(float v){
    __half h=__float2half_rn(v);
    __half l=__float2half_rn(v-__half2float(h));
    return (u32)__half_as_ushort(h) | ((u32)__half_as_ushort(l)<<16);
}
__device__ __forceinline__ u32 packW2(float v){
    __half h=__float2half_rn(v);
    u32 s=__half_as_ushort(h);
    return s|(s<<16);
}
__device__ __forceinline__ void ldmx4(u32* r, u32 addr){
    asm volatile("ldmatrix.sync.aligned.m8n8.x4.shared.b16 {%0,%1,%2,%3}, [%4];"
        :"=r"(r[0]),"=r"(r[1]),"=r"(r[2]),"=r"(r[3]):"r"(addr));
}
__device__ __forceinline__ void mma16816(float* d, const u32* a, const u32* b){
    asm volatile("mma.sync.aligned.m16n8k16.row.col.f32.f16.f16.f32 "
        "{%0,%1,%2,%3},{%4,%5,%6,%7},{%8,%9},{%0,%1,%2,%3};"
        :"+f"(d[0]),"+f"(d[1]),"+f"(d[2]),"+f"(d[3])
        :"r"(a[0]),"r"(a[1]),"r"(a[2]),"r"(a[3]),"r"(b[0]),"r"(b[1]));
}
__device__ __forceinline__ void cpasync16(u32 sm, const void* g){
    asm volatile("cp.async.cg.shared.global [%0],[%1],16;"::"r"(sm),"l"(g):"memory");
}
#define CP_COMMIT() asm volatile("cp.async.commit_group;":::"memory")
#define CP_WAIT1()  asm volatile("cp.async.wait_group 1;":::"memory")
#define CP_WAIT0()  asm volatile("cp.async.wait_group 0;":::"memory")
#define SW(q,r) ((((( (q)>>1)^((r)&7))<<1))|((q)&1))

// ---------- launch 1: GCN linear | degree | weight split | zero A0 | fc_w transpose ----------
__global__ void k_pre(const float* __restrict__ x, const float* __restrict__ w,
                      const int* __restrict__ dst,
                      const float* __restrict__ cw1, const float* __restrict__ dw1,
                      const float* __restrict__ cw2, const float* __restrict__ dw2,
                      const float* __restrict__ fcw){
    int bid=blockIdx.x;
    if(bid<NB_LIN){
        __shared__ float sw[INCH*INCH];
        if(threadIdx.x<INCH*INCH) sw[threadIdx.x]=w[threadIdx.x];
        __syncthreads();
        int n=bid*blockDim.x+threadIdx.x; if(n>=NTOT) return;
        float xr[INCH];
#pragma unroll
        for(int i=0;i<INCH;i++) xr[i]=x[n*INCH+i];
#pragma unroll
        for(int c=0;c<INCH;c++){
            float s=0.f;
#pragma unroll
            for(int i=0;i<INCH;i++) s=fmaf(sw[c*INCH+i],xr[i],s);
            g_h[n*INCH+c]=s;
        }
    } else if(bid<NB_LIN+NB_DEG){
        int e=(bid-NB_LIN)*blockDim.x+threadIdx.x;
        if(e<EDGES) atomicAdd(&g_deg[dst[e]],1.0f);
    } else if(bid<NB_LIN+NB_DEG+NB_WS){
        int i=(bid-NB_LIN-NB_DEG)*256+threadIdx.x;
        if(i<C1*4*C0){
            int oc=i/(4*C0), g=(i/C0)%4, ic=i%C0;
            float v = g<3 ? cw1[(oc*C0+ic)*3+g] : dw1[oc*C0+ic];
            ((u32*)g_W1s)[((size_t)oc*4+g)*C0 + ((ic>>5)*16+SW((ic>>1)&15,oc))*2 + (ic&1)]=packW2(v);
        } else {
            i-=C1*4*C0;
            if(i<C2*4*C1){
                int oc=i/(4*C1), g=(i/C1)%4, ic=i%C1;
                float v = g<3 ? cw2[(oc*C1+ic)*3+g] : dw2[oc*C1+ic];
                ((u32*)g_W2s)[((size_t)oc*4+g)*C1 + ((ic>>5)*16+SW((ic>>1)&15,oc))*2 + (ic&1)]=packW2(v);
            }
        }
    } else if(bid<NB_LIN+NB_DEG+NB_WS+NB_Z){
        int i=(bid-NB_LIN-NB_DEG-NB_WS)*256+threadIdx.x;
        if(i<NTOT*INCH) g_A0[i]=0.f;
    } else {
        int i=(bid-NB_LIN-NB_DEG-NB_WS-NB_Z)*256+threadIdx.x;
        if(i<FCOUT*FCIN){
            int o=i/FCIN, r=i%FCIN, tt=r/C2, cc=r%C2;
            g_Wfc[i]=fcw[(size_t)o*FCIN + cc*NODES + tt];
        }
    }
}

// ---------- launch 2: node init + edge scatter, (e,c)-parallel atomics ----------
__global__ void k_scatter(const int* __restrict__ src, const int* __restrict__ dst,
                          const float* __restrict__ gcn_b){
    int bid=blockIdx.x;
    if(bid<NB_NI){
        int id=bid*256+threadIdx.x; if(id>=NTOT*INCH) return;
        int n=id/INCH, c=id%INCH;
        float di2=__frcp_rn(g_deg[n]+1.0f);
        atomicAdd(&g_A0[id], fmaf(di2,g_h[id],gcn_b[c]));
    } else {
        int id=(bid-NB_NI)*256+threadIdx.x; if(id>=EDGES*INCH) return;
        int e=id/INCH, c=id%INCH;
        int s=src[e], d=dst[e];
        float sc=rsqrtf(g_deg[s]+1.0f)*rsqrtf(g_deg[d]+1.0f);
        atomicAdd(&g_A0[d*INCH+c], sc*g_h[s*INCH+c]);
    }
}

// ---------- launch 3: tcn0 scalar (12->128), emits swizzled f16-pair stream ----------
__global__ void __launch_bounds__(256,2)
k_tcn0(const float* __restrict__ cw, const float* __restrict__ cb,
       const float* __restrict__ dw, const float* __restrict__ db){
    constexpr int IN=INCH, BN=128, BM=64, NT=256, BK=12;
    __shared__ __align__(16) char smem[43008];
    float* A_s=(float*)smem;
    float* B_s=(float*)(smem+18432);
    const int t=blockIdx.x, b0=blockIdx.y*BN, oc0=blockIdx.z*BM;
    const int tid=threadIdx.x, tx=tid&31, ty=tid>>5;
    const int bb=tx*4, oct=ty*8;
    ull acc1[8][2], acc2[8][2];
#pragma unroll
    for(int j=0;j<8;j++){acc1[j][0]=acc1[j][1]=acc2[j][0]=acc2[j][1]=0ULL;}
    for(int i=tid;i<BK*3*BN;i+=NT){
        int ic=i/(3*BN), r=i%(3*BN), kk=r/BN, b=r%BN;
        int tk=t+(kk-2);
        A_s[i]=(tk>=0)?g_A0[((size_t)(b0+b)*NODES+tk)*IN+ic]:0.f;
    }
    for(int i=tid;i<BM*BK*4;i+=NT){
        int oc=i/(BK*4), r=i%(BK*4), ic=r/4, w=r&3;
        float v=(w<3)?cw[((size_t)(oc0+oc)*IN+ic)*3+w]:dw[(size_t)(oc0+oc)*IN+ic];
        *reinterpret_cast<ull*>(&B_s[i*2])=dup2(v);
    }
    __syncthreads();
#pragma unroll
    for(int ic=0;ic<BK;ic++){
        ulonglong2 a0=*reinterpret_cast<const ulonglong2*>(&A_s[(ic*3+0)*BN+bb]);
        ulonglong2 a1=*reinterpret_cast<const ulonglong2*>(&A_s[(ic*3+1)*BN+bb]);
        ulonglong2 a2=*reinterpret_cast<const ulonglong2*>(&A_s[(ic*3+2)*BN+bb]);
#pragma unroll
        for(int j=0;j<8;j++){
            const float* wb=&B_s[((oct+j)*BK+ic)*8];
            ulonglong2 wA=*reinterpret_cast<const ulonglong2*>(wb);
            ulonglong2 wB=*reinterpret_cast<const ulonglong2*>(wb+4);
            fma2(acc1[j][0],wA.x,a0.x); fma2(acc1[j][1],wA.x,a0.y);
            fma2(acc1[j][0],wA.y,a1.x); fma2(acc1[j][1],wA.y,a1.y);
            fma2(acc1[j][0],wB.x,a2.x); fma2(acc1[j][1],wB.x,a2.y);
            fma2(acc2[j][0],wB.y,a2.x); fma2(acc2[j][1],wB.y,a2.y);
        }
    }
    u32* P=(u32*)g_X1s;
#pragma unroll
    for(int j=0;j<8;j++){
        int oc=oc0+oct+j;
        float cbv=cb[oc], dbv=db[oc];
        float c0,c1,c2,c3,d0,d1,d2,d3;
        unpack2(acc1[j][0],c0,c1); unpack2(acc1[j][1],c2,c3);
        unpack2(acc2[j][0],d0,d1); unpack2(acc2[j][1],d2,d3);
        float o[4]={fmaxf(fmaxf(c0+cbv,0.f)+d0+dbv,0.f), fmaxf(fmaxf(c1+cbv,0.f)+d1+dbv,0.f),
                    fmaxf(fmaxf(c2+cbv,0.f)+d2+dbv,0.f), fmaxf(fmaxf(c3+cbv,0.f)+d3+dbv,0.f)};
#pragma unroll
        for(int i=0;i<4;i++){
            int b=b0+bb+i;
            P[((size_t)t*BATCH+b)*C0 + ((oc>>5)*16+SW((oc>>1)&15,b))*2 + (oc&1)]=packA2(o[i]);
        }
    }
}

// ---------- tensor TCN: M=64 x N=128, double-buffered cp.async, zero-pass skipping ----------
template<int IN,int DIL,int OUTM>
__device__ __forceinline__ void tcnT(const ull* __restrict__ Xs, const ull* __restrict__ Ws,
      const float* __restrict__ cb, const float* __restrict__ db, char* smem){
    constexpr int RW2=IN/4;          // u128 per row
    constexpr int CH=RW2/8;          // chunks per pass
    const int t=blockIdx.x, b0=blockIdx.y*64, oc0=blockIdx.z*128;
    const int tid=threadIdx.x, lane=tid&31, w=tid>>5;
    const int mw=w&1, nw=w>>1;
    const u32 Sb=(u32)__cvta_generic_to_shared(smem);
    const int sub=lane>>3, l7=lane&7;
    const int rA0=mw*32+l7+((sub&1)<<3);
    const int rB0=nw*32+l7+((sub>>1)<<3);
    const int uA=sub>>1, uB=sub&1;
    const u128* Xv=(const u128*)Xs;
    const u128* Wv=(const u128*)Ws;
    float accD[2][4][4]={}, accE[2][4][4]={};

    // active pass list (zero taps skipped — they contribute exactly 0)
    int gl[4]; int ng=0;
    if(t-2*DIL>=0) gl[ng++]=0;
    if(t-DIL>=0)   gl[ng++]=1;
    gl[ng++]=2;
    gl[ng++]=3;
    const int NCH=ng*CH;

    auto stage=[&](int j,int buf){
        int g=gl[j/CH], kc=j%CH;
        int tk=(g<3)? t-(2-g)*DIL : t;
        u32 aB=Sb+buf*8192, bB=Sb+16384+buf*16384;
#pragma unroll
        for(int i=tid;i<512;i+=256)
            cpasync16(aB+i*16, &Xv[((size_t)tk*BATCH+b0+(i>>3))*RW2+kc*8+(i&7)]);
#pragma unroll
        for(int i=tid;i<1024;i+=256)
            cpasync16(bB+i*16, &Wv[((size_t)(oc0+(i>>3))*4+g)*RW2+kc*8+(i&7)]);
        CP_COMMIT();
    };

    stage(0,0);
    for(int j=0;j<NCH;j++){
        int buf=j&1;
        if(j+1<NCH){ stage(j+1,1-buf); CP_WAIT1(); }
        else CP_WAIT0();
        __syncthreads();
        const u32 aB=Sb+buf*8192, bB=Sb+16384+buf*16384;
        bool isD = gl[j/CH]<3;
#pragma unroll
        for(int s=0;s<4;s++){
            u32 Af[2][4], Bf[2][4];
#pragma unroll
            for(int mi=0;mi<2;mi++){
                int r=rA0+mi*16, u=2*s+uA;
                ldmx4(Af[mi], aB+(u32)(r*128+((u^(r&7))<<4)));
            }
#pragma unroll
            for(int p=0;p<2;p++){
                int r=rB0+p*16, u=2*s+uB;
                ldmx4(Bf[p], bB+(u32)(r*128+((u^(r&7))<<4)));
            }
            if(isD){
#pragma unroll
                for(int mi=0;mi<2;mi++)
#pragma unroll
                for(int ni=0;ni<4;ni++)
                    mma16816(accD[mi][ni], Af[mi], &Bf[ni>>1][(ni&1)*2]);
            } else {
#pragma unroll
                for(int mi=0;mi<2;mi++)
#pragma unroll
                for(int ni=0;ni<4;ni++)
                    mma16816(accE[mi][ni], Af[mi], &Bf[ni>>1][(ni&1)*2]);
            }
        }
        __syncthreads();
    }
    const int qr=lane>>2, qc=(lane&3)*2;
#pragma unroll
    for(int mi=0;mi<2;mi++)
#pragma unroll
    for(int ni=0;ni<4;ni++){
        int oc=oc0+nw*32+ni*8+qc;
        int b =b0+mw*32+mi*16+qr;
        float cb0=cb[oc], cb1=cb[oc+1], db0=db[oc], db1=db[oc+1];
        const float* D=accD[mi][ni]; const float* E=accE[mi][ni];
        float v00=fmaxf(fmaxf(D[0]+cb0,0.f)+E[0]+db0,0.f);
        float v01=fmaxf(fmaxf(D[1]+cb1,0.f)+E[1]+db1,0.f);
        float v10=fmaxf(fmaxf(D[2]+cb0,0.f)+E[2]+db0,0.f);
        float v11=fmaxf(fmaxf(D[3]+cb1,0.f)+E[3]+db1,0.f);
        if(OUTM==0){
            int qu=oc>>1, kc=qu>>4, q=qu&15;
            g_X2s[((size_t)t*BATCH+b)*(C1/2)+kc*16+SW(q,b)]
                = (ull)packA2(v00) | ((ull)packA2(v01)<<32);
            g_X2s[((size_t)t*BATCH+b+8)*(C1/2)+kc*16+SW(q,b+8)]
                = (ull)packA2(v10) | ((ull)packA2(v11)<<32);
        } else {
            float2 p0; p0.x=v00; p0.y=v01;
            float2 p1; p1.x=v10; p1.y=v11;
            *(float2*)&g_X3[((size_t)t*BATCH+b)*C2+oc]=p0;
            *(float2*)&g_X3[((size_t)t*BATCH+b+8)*C2+oc]=p1;
        }
    }
}
__global__ void __launch_bounds__(256,2)
k_tcn1(const float* __restrict__ cb, const float* __restrict__ db){
    __shared__ __align__(16) char smem[49152];
    tcnT<C0,3,0>(g_X1s, g_W1s, cb, db, smem);
}
__global__ void __launch_bounds__(256,2)
k_tcn2(const float* __restrict__ cb, const float* __restrict__ db){
    __shared__ __align__(16) char smem[49152];
    tcnT<C1,9,1>(g_X2s, g_W2s, cb, db, smem);
}

// ---------- FC on [t][b][c] activations and pre-transposed weights ----------
#define FC_BM 32
#define FC_BK 32
__global__ void __launch_bounds__(256)
k_fc(const float* __restrict__ bias, float* __restrict__ out){
    __shared__ float Ts[FC_BK][FC_BM+1];
    __shared__ float Ws2[80][FC_BK+1];
    int b0=blockIdx.x*FC_BM, tid=threadIdx.x, tr=tid/16, tc=tid%16;
    float acc[2][5]={};
    for(int k0=0;k0<FCIN;k0+=FC_BK){
        int tt=k0>>7, c0=k0&127;            // 32 | 128 -> tile spans one t
        for(int i=tid;i<FC_BK*FC_BM;i+=256){
            int m=i>>5, k=i&31;             // k fastest -> c contiguous, coalesced
            Ts[k][m]=g_X3[((size_t)tt*BATCH+b0+m)*C2+c0+k];
        }
        for(int i=tid;i<80*FC_BK;i+=256){
            int n=i/FC_BK, k=i%FC_BK;
            Ws2[n][k]=(n<FCOUT)?g_Wfc[(size_t)n*FCIN+k0+k]:0.f;
        }
        __syncthreads();
#pragma unroll
        for(int kk=0;kk<FC_BK;kk++){
            float a0=Ts[kk][tr*2+0], a1=Ts[kk][tr*2+1];
#pragma unroll
            for(int j=0;j<5;j++){
                float bv=Ws2[tc*5+j][kk];
                acc[0][j]=fmaf(a0,bv,acc[0][j]);
                acc[1][j]=fmaf(a1,bv,acc[1][j]);
            }
        }
        __syncthreads();
    }
#pragma unroll
    for(int i=0;i<2;i++){
        int b=b0+tr*2+i;
#pragma unroll
        for(int j=0;j<5;j++){
            int o=tc*5+j;
            if(o<FCOUT) out[(size_t)b*FCOUT+o]=acc[i][j]+bias[o];
        }
    }
    for(int i=blockIdx.x*256+tid;i<NTOT;i+=gridDim.x*256) g_deg[i]=0.f;
}

// ---------- launch (tcn1 is launch #4 for ncu) ----------
extern "C" void kernel_launch(void* const* d_in, const int* in_sizes, int n_in,
                              void* d_out, int out_size){
    const float* x=(const float*)d_in[0];
    const int* ei=(const int*)d_in[1];
    const float* gcn_w=(const float*)d_in[2];
    const float* gcn_b=(const float*)d_in[3];
    const float* cw0=(const float*)d_in[4];
    const float* cb0=(const float*)d_in[5];
    const float* dw0=(const float*)d_in[6];
    const float* db0=(const float*)d_in[7];
    const float* cw1=(const float*)d_in[8];
    const float* cb1=(const float*)d_in[9];
    const float* dw1=(const float*)d_in[10];
    const float* db1=(const float*)d_in[11];
    const float* cw2=(const float*)d_in[12];
    const float* cb2=(const float*)d_in[13];
    const float* dw2=(const float*)d_in[14];
    const float* db2=(const float*)d_in[15];
    const float* fc_w=(const float*)d_in[16];
    const float* fc_b=(const float*)d_in[17];
    float* out=(float*)d_out;
    const int* src=ei;
    const int* dst=ei+EDGES;

    k_pre<<<NB_LIN+NB_DEG+NB_WS+NB_Z+NB_WT,256>>>(x,gcn_w,dst,cw1,dw1,cw2,dw2,fc_w);
    k_scatter<<<NB_NI+NB_ES,256>>>(src,dst,gcn_b);
    k_tcn0<<<dim3(NODES,BATCH/128,C0/64),256>>>(cw0,cb0,dw0,db0);
    k_tcn1<<<dim3(NODES,BATCH/64,C1/128),256>>>(cb1,db1);
    k_tcn2<<<dim3(NODES,BATCH/64,C2/128),256>>>(cb2,db2);
    k_fc<<<BATCH/FC_BM,256>>>(fc_b,out);
}